// round 1
// baseline (speedup 1.0000x reference)
#include <cuda_runtime.h>

// Problem constants (shapes fixed by the dataset; runtime sizes read from in_sizes)
#define MAXN 100000
#define MAXE 200000

// -------- scratch (static device globals; no allocation) --------
__device__ float g_we[(size_t)MAXE * 1024];   // 819.2 MB  edge-conditioned weights [E][32*32] (in-major, out-minor)
__device__ float g_out[MAXN * 32];            // current node state (out == h)
__device__ float g_agg[MAXN * 32];            // scatter accumulator
__device__ float g_cnt[MAXN];                 // in-degree counts

// -------- packed f32x2 helpers --------
__device__ __forceinline__ unsigned long long pack2(float lo, float hi) {
    unsigned long long r;
    asm("mov.b64 %0, {%1, %2};" : "=l"(r) : "f"(lo), "f"(hi));
    return r;
}
__device__ __forceinline__ void fma2(unsigned long long& d, unsigned long long a, unsigned long long b) {
    asm("fma.rn.f32x2 %0, %1, %2, %0;" : "+l"(d) : "l"(a), "l"(b));
}
__device__ __forceinline__ float2 unpack2(unsigned long long v) {
    float lo, hi;
    asm("mov.b64 {%0, %1}, %2;" : "=f"(lo), "=f"(hi) : "l"(v));
    return make_float2(lo, hi);
}

// ============================================================
// init: zero agg + cnt
// ============================================================
__global__ void k_init(int n) {
    int t = blockIdx.x * blockDim.x + threadIdx.x;
    int stride = gridDim.x * blockDim.x;
    for (int i = t; i < n * 32; i += stride) g_agg[i] = 0.f;
    for (int i = t; i < n; i += stride) g_cnt[i] = 0.f;
}

// count in-degree by dst
__global__ void k_count(const int* __restrict__ dst, int e) {
    int t = blockIdx.x * blockDim.x + threadIdx.x;
    if (t < e) atomicAdd(&g_cnt[dst[t]], 1.f);
}

// ============================================================
// lin0: out = relu(x @ lin0_w^T + b)   [N,16] -> [N,32]
// warp per node, lane = output dim
// ============================================================
__global__ void k_lin0(const float* __restrict__ x, const float* __restrict__ w,
                       const float* __restrict__ b, int n) {
    __shared__ float wT[16 * 32];
    __shared__ float bs[32];
    int t = threadIdx.x;
    for (int i = t; i < 512; i += blockDim.x) {
        int d = i >> 4, k = i & 15;
        wT[k * 32 + d] = w[i];
    }
    if (t < 32) bs[t] = b[t];
    __syncthreads();

    int warp = (blockIdx.x * blockDim.x + t) >> 5;
    int lane = t & 31;
    if (warp >= n) return;
    float xk = (lane < 16) ? x[(size_t)warp * 16 + lane] : 0.f;
    float acc = bs[lane];
#pragma unroll
    for (int k = 0; k < 16; k++) {
        float xv = __shfl_sync(0xffffffffu, xk, k);
        acc = fmaf(wT[k * 32 + lane], xv, acc);
    }
    g_out[(size_t)warp * 32 + lane] = fmaxf(acc, 0.f);
}

// ============================================================
// w_e GEMM:  w_e[e][c] = b2[c] + sum_h relu(ea[e]@W1^T+b1)[h] * W2[c][h]
// Tile: 128 edges x 128 cols, K=128 fully smem-resident (no k-tiling).
// Per thread: 8 edges x 8 cols (4 f32x2 col-pairs), packed-f32x2 FMA.
// ============================================================
#define WE_RT_STRIDE 128
#define WE_W2_STRIDE 130
#define WE_SMEM_BYTES ((128 * WE_RT_STRIDE + 128 * WE_W2_STRIDE) * 4)

__global__ __launch_bounds__(256) void k_we(
    const float* __restrict__ ea, const float* __restrict__ w1,
    const float* __restrict__ b1, const float* __restrict__ w2,
    const float* __restrict__ b2, int E)
{
    extern __shared__ float sm[];
    float* rT = sm;                        // [k][e], stride 128
    float* w2T = sm + 128 * WE_RT_STRIDE;  // [k][c], stride 130 (pad -> conflict-free paired loads)
    __shared__ float eas[128 * 5];

    const int t = threadIdx.x;
    const int ebase = blockIdx.y * 128;
    const int cbase = blockIdx.x * 128;

    // stage edge_attr tile
    for (int i = t; i < 128 * 5; i += 256) {
        int el = i / 5, j = i - el * 5;
        int ge = ebase + el;
        eas[i] = (ge < E) ? ea[(size_t)ge * 5 + j] : 0.f;
    }
    // stage W2 tile, transposed to [k][c]
    for (int i = t; i < 16384; i += 256) {
        int c = i >> 7, k = i & 127;
        w2T[k * WE_W2_STRIDE + c] = w2[(size_t)(cbase + c) * 128 + k];
    }
    __syncthreads();

    // compute hidden r tile in-smem (transposed [h][e])
    for (int q = 0; q < 64; q++) {
        int idx = q * 256 + t;
        int el = idx & 127, h = idx >> 7;
        float acc = __ldg(&b1[h]);
#pragma unroll
        for (int j = 0; j < 5; j++)
            acc = fmaf(eas[el * 5 + j], __ldg(&w1[h * 5 + j]), acc);
        rT[h * WE_RT_STRIDE + el] = fmaxf(acc, 0.f);
    }
    __syncthreads();

    const int tx = t & 15;   // col-pair group: pairs {tx, tx+16, tx+32, tx+48}
    const int ty = t >> 4;   // edge group: edges ty*8 .. ty*8+7

    unsigned long long acc[8][4];
#pragma unroll
    for (int i = 0; i < 8; i++)
#pragma unroll
        for (int j = 0; j < 4; j++) acc[i][j] = 0ull;

#pragma unroll 8
    for (int k = 0; k < 128; k++) {
        const float* rrow = &rT[k * WE_RT_STRIDE + ty * 8];
        float4 a0 = *(const float4*)(rrow);
        float4 a1 = *(const float4*)(rrow + 4);
        unsigned long long A[8];
        A[0] = pack2(a0.x, a0.x); A[1] = pack2(a0.y, a0.y);
        A[2] = pack2(a0.z, a0.z); A[3] = pack2(a0.w, a0.w);
        A[4] = pack2(a1.x, a1.x); A[5] = pack2(a1.y, a1.y);
        A[6] = pack2(a1.z, a1.z); A[7] = pack2(a1.w, a1.w);
        unsigned long long B[4];
#pragma unroll
        for (int j = 0; j < 4; j++)
            B[j] = *(const unsigned long long*)&w2T[k * WE_W2_STRIDE + 2 * (tx + 16 * j)];
#pragma unroll
        for (int i = 0; i < 8; i++)
#pragma unroll
            for (int j = 0; j < 4; j++)
                fma2(acc[i][j], A[i], B[j]);
    }

    // epilogue: add b2, store fp32 (coalesced float2, cols even)
#pragma unroll
    for (int i = 0; i < 8; i++) {
        int ge = ebase + ty * 8 + i;
        if (ge >= E) continue;
        float* dstp = &g_we[(size_t)ge * 1024 + cbase];
#pragma unroll
        for (int j = 0; j < 4; j++) {
            int c = 2 * (tx + 16 * j);
            float2 v = unpack2(acc[i][j]);
            v.x += __ldg(&b2[cbase + c]);
            v.y += __ldg(&b2[cbase + c + 1]);
            *(float2*)(dstp + c) = v;
        }
    }
}

// ============================================================
// message pass: msg[e,o] = sum_i out[src[e]][i] * w_e[e][i*32+o]
// then scatter-add into agg[dst]. Warp per edge, lane = o.
// ============================================================
__global__ void k_msg(const int* __restrict__ src, const int* __restrict__ dst, int e) {
    int warp = (blockIdx.x * blockDim.x + threadIdx.x) >> 5;
    int lane = threadIdx.x & 31;
    if (warp >= e) return;
    int s = __ldg(&src[warp]);
    int d = __ldg(&dst[warp]);
    float sv = g_out[(size_t)s * 32 + lane];
    const float* w = &g_we[(size_t)warp * 1024];
    float acc = 0.f;
#pragma unroll
    for (int i = 0; i < 32; i++) {
        float si = __shfl_sync(0xffffffffu, sv, i);
        acc = fmaf(si, w[i * 32 + lane], acc);
    }
    atomicAdd(&g_agg[(size_t)d * 32 + lane], acc);
}

// ============================================================
// fused NNConv-root + GRU update (warp per node), re-zeros agg
// ============================================================
__global__ void k_update(const float* __restrict__ root_w, const float* __restrict__ conv_b,
                         const float* __restrict__ wih, const float* __restrict__ whh,
                         const float* __restrict__ bih, const float* __restrict__ bhh, int n) {
    __shared__ float rootT[32 * 33];   // [j][d], pad 33 -> conflict-free
    __shared__ float wihT[32 * 97];    // [j][row], pad 97
    __shared__ float whhT[32 * 97];
    __shared__ float cb[32], bi[96], bh[96];
    int t = threadIdx.x;
    for (int i = t; i < 1024; i += blockDim.x) {
        int d = i >> 5, j = i & 31;
        rootT[j * 33 + d] = root_w[i];
    }
    for (int i = t; i < 3072; i += blockDim.x) {
        int rr = i >> 5, j = i & 31;
        wihT[j * 97 + rr] = wih[i];
        whhT[j * 97 + rr] = whh[i];
    }
    if (t < 32) cb[t] = conv_b[t];
    if (t < 96) { bi[t] = bih[t]; bh[t] = bhh[t]; }
    __syncthreads();

    int warp = (blockIdx.x * blockDim.x + t) >> 5;
    int lane = t & 31;
    if (warp >= n) return;
    size_t base = (size_t)warp * 32 + lane;

    float h = g_out[base];
    float c = fmaxf(g_cnt[warp], 1.f);
    float m = g_agg[base] / c + cb[lane];
#pragma unroll
    for (int j = 0; j < 32; j++) {
        float hj = __shfl_sync(0xffffffffu, h, j);
        m = fmaf(rootT[j * 33 + lane], hj, m);
    }
    m = fmaxf(m, 0.f);

    float gr = bi[lane], gz = bi[32 + lane], gn = bi[64 + lane];
    float hr = bh[lane], hz = bh[32 + lane], hn = bh[64 + lane];
#pragma unroll
    for (int j = 0; j < 32; j++) {
        float mj = __shfl_sync(0xffffffffu, m, j);
        float hj = __shfl_sync(0xffffffffu, h, j);
        gr = fmaf(wihT[j * 97 + lane], mj, gr);
        gz = fmaf(wihT[j * 97 + 32 + lane], mj, gz);
        gn = fmaf(wihT[j * 97 + 64 + lane], mj, gn);
        hr = fmaf(whhT[j * 97 + lane], hj, hr);
        hz = fmaf(whhT[j * 97 + 32 + lane], hj, hz);
        hn = fmaf(whhT[j * 97 + 64 + lane], hj, hn);
    }
    float r = 1.f / (1.f + __expf(-(gr + hr)));
    float z = 1.f / (1.f + __expf(-(gz + hz)));
    float nn = tanhf(gn + r * hn);
    float hnew = (1.f - z) * nn + z * h;

    g_out[base] = hnew;
    g_agg[base] = 0.f;   // pre-zero for next iteration's scatter
}

// ============================================================
// final: y = relu(out @ lin1^T + b1) @ lin2^T + b2   -> [N,1]
// ============================================================
__global__ void k_final(const float* __restrict__ l1w, const float* __restrict__ l1b,
                        const float* __restrict__ l2w, const float* __restrict__ l2b,
                        float* __restrict__ out, int n) {
    __shared__ float w1T[32 * 33];
    __shared__ float b1s[32], w2s[32];
    int t = threadIdx.x;
    for (int i = t; i < 1024; i += blockDim.x) {
        int d = i >> 5, j = i & 31;
        w1T[j * 33 + d] = l1w[i];
    }
    if (t < 32) { b1s[t] = l1b[t]; w2s[t] = l2w[t]; }
    __syncthreads();

    int warp = (blockIdx.x * blockDim.x + t) >> 5;
    int lane = t & 31;
    if (warp >= n) return;
    float h = g_out[(size_t)warp * 32 + lane];
    float acc = b1s[lane];
#pragma unroll
    for (int j = 0; j < 32; j++) {
        float hj = __shfl_sync(0xffffffffu, h, j);
        acc = fmaf(w1T[j * 33 + lane], hj, acc);
    }
    acc = fmaxf(acc, 0.f);
    float p = acc * w2s[lane];
#pragma unroll
    for (int off = 16; off; off >>= 1) p += __shfl_xor_sync(0xffffffffu, p, off);
    if (lane == 0) out[warp] = p + __ldg(&l2b[0]);
}

// ============================================================
// launcher
// ============================================================
extern "C" void kernel_launch(void* const* d_in, const int* in_sizes, int n_in,
                              void* d_out, int out_size) {
    const float* x      = (const float*)d_in[0];
    const int*   ei     = (const int*)  d_in[1];
    const float* ea     = (const float*)d_in[2];
    const float* lin0_w = (const float*)d_in[3];
    const float* lin0_b = (const float*)d_in[4];
    const float* mlp_w1 = (const float*)d_in[5];
    const float* mlp_b1 = (const float*)d_in[6];
    const float* mlp_w2 = (const float*)d_in[7];
    const float* mlp_b2 = (const float*)d_in[8];
    const float* root_w = (const float*)d_in[9];
    const float* conv_b = (const float*)d_in[10];
    const float* gw_ih  = (const float*)d_in[11];
    const float* gw_hh  = (const float*)d_in[12];
    const float* gb_ih  = (const float*)d_in[13];
    const float* gb_hh  = (const float*)d_in[14];
    const float* lin1_w = (const float*)d_in[15];
    const float* lin1_b = (const float*)d_in[16];
    const float* lin2_w = (const float*)d_in[17];
    const float* lin2_b = (const float*)d_in[18];

    const int n = in_sizes[0] / 16;   // 100000
    const int e = in_sizes[2] / 5;    // 200000
    const int* src = ei;
    const int* dst = ei + e;

    cudaFuncSetAttribute(k_we, cudaFuncAttributeMaxDynamicSharedMemorySize, WE_SMEM_BYTES);

    // init + degree count
    k_init<<<1024, 256>>>(n);
    k_count<<<(e + 255) / 256, 256>>>(dst, e);

    // lin0
    k_lin0<<<(n * 32 + 255) / 256, 256>>>(x, lin0_w, lin0_b, n);

    // edge-conditioned weights (hoisted, computed once)
    dim3 wgrid(8, (e + 127) / 128);
    k_we<<<wgrid, 256, WE_SMEM_BYTES>>>(ea, mlp_w1, mlp_b1, mlp_w2, mlp_b2, e);

    // 3 message-passing + GRU iterations
    for (int it = 0; it < 3; it++) {
        k_msg<<<(e * 32 + 255) / 256, 256>>>(src, dst, e);
        k_update<<<(n * 32 + 511) / 512, 512>>>(root_w, conv_b, gw_ih, gw_hh, gb_ih, gb_hh, n);
    }

    // readout
    k_final<<<(n * 32 + 255) / 256, 256>>>(lin1_w, lin1_b, lin2_w, lin2_b, (float*)d_out, n);
}

// round 4
// speedup vs baseline: 1.1884x; 1.1884x over previous
#include <cuda_runtime.h>
#include <cuda_fp16.h>

// Problem constants
#define MAXN 100000
#define MAXE 200000

// -------- scratch (static device globals; no allocation) --------
// w_e stored fp16, TRANSPOSED per edge: g_weh[e][o][i] at offset e*1024 + o*32 + i
__device__ __half g_weh[(size_t)MAXE * 1024];   // 409.6 MB
__device__ float g_out[MAXN * 32];              // current node state
__device__ float g_agg[MAXN * 32];              // scatter accumulator
__device__ float g_cnt[MAXN];                   // in-degree counts

// -------- packed f32x2 helpers --------
__device__ __forceinline__ unsigned long long pack2(float lo, float hi) {
    unsigned long long r;
    asm("mov.b64 %0, {%1, %2};" : "=l"(r) : "f"(lo), "f"(hi));
    return r;
}
__device__ __forceinline__ void fma2(unsigned long long& d, unsigned long long a, unsigned long long b) {
    asm("fma.rn.f32x2 %0, %1, %2, %0;" : "+l"(d) : "l"(a), "l"(b));
}
__device__ __forceinline__ float2 unpack2(unsigned long long v) {
    float lo, hi;
    asm("mov.b64 {%0, %1}, %2;" : "=f"(lo), "=f"(hi) : "l"(v));
    return make_float2(lo, hi);
}

// ============================================================
// init: zero agg + cnt
// ============================================================
__global__ void k_init(int n) {
    int t = blockIdx.x * blockDim.x + threadIdx.x;
    int stride = gridDim.x * blockDim.x;
    for (int i = t; i < n * 32; i += stride) g_agg[i] = 0.f;
    for (int i = t; i < n; i += stride) g_cnt[i] = 0.f;
}

__global__ void k_count(const int* __restrict__ dst, int e) {
    int t = blockIdx.x * blockDim.x + threadIdx.x;
    if (t < e) atomicAdd(&g_cnt[dst[t]], 1.f);
}

// ============================================================
// lin0: out = relu(x @ lin0_w^T + b)   [N,16] -> [N,32]
// ============================================================
__global__ void k_lin0(const float* __restrict__ x, const float* __restrict__ w,
                       const float* __restrict__ b, int n) {
    __shared__ float wT[16 * 32];
    __shared__ float bs[32];
    int t = threadIdx.x;
    for (int i = t; i < 512; i += blockDim.x) {
        int d = i >> 4, k = i & 15;
        wT[k * 32 + d] = w[i];
    }
    if (t < 32) bs[t] = b[t];
    __syncthreads();

    int warp = (blockIdx.x * blockDim.x + t) >> 5;
    int lane = t & 31;
    if (warp >= n) return;
    float xk = (lane < 16) ? x[(size_t)warp * 16 + lane] : 0.f;
    float acc = bs[lane];
#pragma unroll
    for (int k = 0; k < 16; k++) {
        float xv = __shfl_sync(0xffffffffu, xk, k);
        acc = fmaf(wT[k * 32 + lane], xv, acc);
    }
    g_out[(size_t)warp * 32 + lane] = fmaxf(acc, 0.f);
}

// ============================================================
// w_e GEMM (fp16 output, per-edge transposed layout):
//   g_weh[e][c'] where c' = o*32+i, value = b2[i*32+o] + sum_h r[e,h]*W2[i*32+o, h]
// Transpose is free: the W2 smem staging reads permuted rows.
// Tile: 128 edges x 128 cols, K chunked 2x64 (smem 67KB -> 2 blocks/SM).
// Per thread: 8 edges (ty*8..) x 8 cols (quads 4tx.., 64+4tx..), f32x2 FMA.
// ============================================================
#define WE_SMEM_BYTES ((64 * 128 + 64 * 132) * 4)

__global__ __launch_bounds__(256, 2) void k_we(
    const float* __restrict__ ea, const float* __restrict__ w1,
    const float* __restrict__ b1, const float* __restrict__ w2,
    const float* __restrict__ b2, int E)
{
    extern __shared__ float sm[];
    float* rT  = sm;              // [hh][el], 64 x 128
    float* w2T = sm + 64 * 128;   // [k][c],  64 x 132 (pad 132 keeps 16B align)
    __shared__ float eas[128 * 5];

    const int t = threadIdx.x;
    const int ebase = blockIdx.y * 128;
    const int cbase = blockIdx.x * 128;
    const int tx = t & 15;
    const int ty = t >> 4;

    // stage edge_attr tile (once)
    for (int i = t; i < 640; i += 256) {
        int el = i / 5, j = i - el * 5;
        int ge = ebase + el;
        eas[i] = (ge < E) ? ea[(size_t)ge * 5 + j] : 0.f;
    }

    unsigned long long acc[8][4];
#pragma unroll
    for (int i = 0; i < 8; i++)
#pragma unroll
        for (int j = 0; j < 4; j++) acc[i][j] = 0ull;

    for (int kc = 0; kc < 2; kc++) {
        __syncthreads();  // kc=0: orders eas; kc=1: protects smem reuse
        // stage W2 chunk, permuted transpose: local col c -> global c'=cbase+c,
        // source W2 row = (c'&31)*32 + (c'>>5)   (o,i swap)
        for (int i = t; i < 8192; i += 256) {
            int c = i >> 6, k = i & 63;
            int cg = cbase + c;
            int sr = ((cg & 31) << 5) | (cg >> 5);
            w2T[k * 132 + c] = __ldg(&w2[(size_t)sr * 128 + kc * 64 + k]);
        }
        // compute hidden r chunk (transposed [hh][el])
        for (int i = t; i < 8192; i += 256) {
            int el = i & 127, hh = i >> 7;
            int h = kc * 64 + hh;
            float a = __ldg(&b1[h]);
#pragma unroll
            for (int j = 0; j < 5; j++)
                a = fmaf(eas[el * 5 + j], __ldg(&w1[h * 5 + j]), a);
            rT[hh * 128 + el] = fmaxf(a, 0.f);
        }
        __syncthreads();

#pragma unroll 8
        for (int kk = 0; kk < 64; kk++) {
            const float* rrow = &rT[kk * 128 + ty * 8];
            float4 a0 = *(const float4*)(rrow);
            float4 a1 = *(const float4*)(rrow + 4);
            // B: two LDS.128, each = two pre-packed f32x2 col-pairs
            ulonglong2 bq0 = *(const ulonglong2*)&w2T[kk * 132 + 4 * tx];
            ulonglong2 bq1 = *(const ulonglong2*)&w2T[kk * 132 + 64 + 4 * tx];
            unsigned long long A[8];
            A[0] = pack2(a0.x, a0.x); A[1] = pack2(a0.y, a0.y);
            A[2] = pack2(a0.z, a0.z); A[3] = pack2(a0.w, a0.w);
            A[4] = pack2(a1.x, a1.x); A[5] = pack2(a1.y, a1.y);
            A[6] = pack2(a1.z, a1.z); A[7] = pack2(a1.w, a1.w);
#pragma unroll
            for (int i = 0; i < 8; i++) {
                fma2(acc[i][0], A[i], bq0.x);
                fma2(acc[i][1], A[i], bq0.y);
                fma2(acc[i][2], A[i], bq1.x);
                fma2(acc[i][3], A[i], bq1.y);
            }
        }
    }

    // epilogue: add permuted b2, convert to fp16, store 8B per quad
    float bias[8];
#pragma unroll
    for (int j = 0; j < 8; j++) {
        int c = (j < 4) ? (4 * tx + j) : (64 + 4 * tx + (j - 4));
        int cg = cbase + c;
        int sr = ((cg & 31) << 5) | (cg >> 5);
        bias[j] = __ldg(&b2[sr]);
    }
#pragma unroll
    for (int i = 0; i < 8; i++) {
        int ge = ebase + ty * 8 + i;
        if (ge >= E) continue;
        __half* dp = &g_weh[(size_t)ge * 1024 + cbase];
        float2 v0 = unpack2(acc[i][0]), v1 = unpack2(acc[i][1]);
        float2 v2 = unpack2(acc[i][2]), v3 = unpack2(acc[i][3]);
        union { __half2 h[2]; uint2 u; } q0, q1;
        q0.h[0] = __floats2half2_rn(v0.x + bias[0], v0.y + bias[1]);
        q0.h[1] = __floats2half2_rn(v1.x + bias[2], v1.y + bias[3]);
        q1.h[0] = __floats2half2_rn(v2.x + bias[4], v2.y + bias[5]);
        q1.h[1] = __floats2half2_rn(v3.x + bias[6], v3.y + bias[7]);
        *(uint2*)(dp + 4 * tx) = q0.u;
        *(uint2*)(dp + 64 + 4 * tx) = q1.u;
    }
}

// ============================================================
// message pass: msg[e,o] = sum_i out[src[e]][i] * w_t[e][o][i]
// Warp per edge, lane = o. Lane-private 64B (4x LDG.128) -> dot product.
// Perfectly coalesced 2KB/edge; DRAM-bound.
// ============================================================
__global__ void k_msg(const int* __restrict__ src, const int* __restrict__ dst, int e) {
    int warp = (blockIdx.x * blockDim.x + threadIdx.x) >> 5;
    int lane = threadIdx.x & 31;
    if (warp >= e) return;
    int s = __ldg(&src[warp]);
    int d = __ldg(&dst[warp]);
    const uint4* wp = (const uint4*)(g_weh + (size_t)warp * 1024 + lane * 32);
    uint4 w0 = __ldg(&wp[0]);
    uint4 w1 = __ldg(&wp[1]);
    uint4 w2 = __ldg(&wp[2]);
    uint4 w3 = __ldg(&wp[3]);
    float sv = g_out[(size_t)s * 32 + lane];
    float acc = 0.f;

#define ACC2(u, i0) do { \
        float2 f_ = __half22float2(*(const __half2*)&(u)); \
        acc = fmaf(__shfl_sync(0xffffffffu, sv, (i0)), f_.x, acc); \
        acc = fmaf(__shfl_sync(0xffffffffu, sv, (i0) + 1), f_.y, acc); \
    } while (0)

    ACC2(w0.x, 0);  ACC2(w0.y, 2);  ACC2(w0.z, 4);  ACC2(w0.w, 6);
    ACC2(w1.x, 8);  ACC2(w1.y, 10); ACC2(w1.z, 12); ACC2(w1.w, 14);
    ACC2(w2.x, 16); ACC2(w2.y, 18); ACC2(w2.z, 20); ACC2(w2.w, 22);
    ACC2(w3.x, 24); ACC2(w3.y, 26); ACC2(w3.z, 28); ACC2(w3.w, 30);
#undef ACC2

    atomicAdd(&g_agg[(size_t)d * 32 + lane], acc);
}

// ============================================================
// fused NNConv-root + GRU update (warp per node), re-zeros agg
// ============================================================
__global__ void k_update(const float* __restrict__ root_w, const float* __restrict__ conv_b,
                         const float* __restrict__ wih, const float* __restrict__ whh,
                         const float* __restrict__ bih, const float* __restrict__ bhh, int n) {
    __shared__ float rootT[32 * 33];
    __shared__ float wihT[32 * 97];
    __shared__ float whhT[32 * 97];
    __shared__ float cb[32], bi[96], bh[96];
    int t = threadIdx.x;
    for (int i = t; i < 1024; i += blockDim.x) {
        int d = i >> 5, j = i & 31;
        rootT[j * 33 + d] = root_w[i];
    }
    for (int i = t; i < 3072; i += blockDim.x) {
        int rr = i >> 5, j = i & 31;
        wihT[j * 97 + rr] = wih[i];
        whhT[j * 97 + rr] = whh[i];
    }
    if (t < 32) cb[t] = conv_b[t];
    if (t < 96) { bi[t] = bih[t]; bh[t] = bhh[t]; }
    __syncthreads();

    int warp = (blockIdx.x * blockDim.x + t) >> 5;
    int lane = t & 31;
    if (warp >= n) return;
    size_t base = (size_t)warp * 32 + lane;

    float h = g_out[base];
    float c = fmaxf(g_cnt[warp], 1.f);
    float m = g_agg[base] / c + cb[lane];
#pragma unroll
    for (int j = 0; j < 32; j++) {
        float hj = __shfl_sync(0xffffffffu, h, j);
        m = fmaf(rootT[j * 33 + lane], hj, m);
    }
    m = fmaxf(m, 0.f);

    float gr = bi[lane], gz = bi[32 + lane], gn = bi[64 + lane];
    float hr = bh[lane], hz = bh[32 + lane], hn = bh[64 + lane];
#pragma unroll
    for (int j = 0; j < 32; j++) {
        float mj = __shfl_sync(0xffffffffu, m, j);
        float hj = __shfl_sync(0xffffffffu, h, j);
        gr = fmaf(wihT[j * 97 + lane], mj, gr);
        gz = fmaf(wihT[j * 97 + 32 + lane], mj, gz);
        gn = fmaf(wihT[j * 97 + 64 + lane], mj, gn);
        hr = fmaf(whhT[j * 97 + lane], hj, hr);
        hz = fmaf(whhT[j * 97 + 32 + lane], hj, hz);
        hn = fmaf(whhT[j * 97 + 64 + lane], hj, hn);
    }
    float r = 1.f / (1.f + __expf(-(gr + hr)));
    float z = 1.f / (1.f + __expf(-(gz + hz)));
    float nn = tanhf(gn + r * hn);
    float hnew = (1.f - z) * nn + z * h;

    g_out[base] = hnew;
    g_agg[base] = 0.f;
}

// ============================================================
// final: y = relu(out @ lin1^T + b1) @ lin2^T + b2   -> [N,1]
// ============================================================
__global__ void k_final(const float* __restrict__ l1w, const float* __restrict__ l1b,
                        const float* __restrict__ l2w, const float* __restrict__ l2b,
                        float* __restrict__ out, int n) {
    __shared__ float w1T[32 * 33];
    __shared__ float b1s[32], w2s[32];
    int t = threadIdx.x;
    for (int i = t; i < 1024; i += blockDim.x) {
        int d = i >> 5, j = i & 31;
        w1T[j * 33 + d] = l1w[i];
    }
    if (t < 32) { b1s[t] = l1b[t]; w2s[t] = l2w[t]; }
    __syncthreads();

    int warp = (blockIdx.x * blockDim.x + t) >> 5;
    int lane = t & 31;
    if (warp >= n) return;
    float h = g_out[(size_t)warp * 32 + lane];
    float acc = b1s[lane];
#pragma unroll
    for (int j = 0; j < 32; j++) {
        float hj = __shfl_sync(0xffffffffu, h, j);
        acc = fmaf(w1T[j * 33 + lane], hj, acc);
    }
    acc = fmaxf(acc, 0.f);
    float p = acc * w2s[lane];
#pragma unroll
    for (int off = 16; off; off >>= 1) p += __shfl_xor_sync(0xffffffffu, p, off);
    if (lane == 0) out[warp] = p + __ldg(&l2b[0]);
}

// ============================================================
// launcher
// ============================================================
extern "C" void kernel_launch(void* const* d_in, const int* in_sizes, int n_in,
                              void* d_out, int out_size) {
    const float* x      = (const float*)d_in[0];
    const int*   ei     = (const int*)  d_in[1];
    const float* ea     = (const float*)d_in[2];
    const float* lin0_w = (const float*)d_in[3];
    const float* lin0_b = (const float*)d_in[4];
    const float* mlp_w1 = (const float*)d_in[5];
    const float* mlp_b1 = (const float*)d_in[6];
    const float* mlp_w2 = (const float*)d_in[7];
    const float* mlp_b2 = (const float*)d_in[8];
    const float* root_w = (const float*)d_in[9];
    const float* conv_b = (const float*)d_in[10];
    const float* gw_ih  = (const float*)d_in[11];
    const float* gw_hh  = (const float*)d_in[12];
    const float* gb_ih  = (const float*)d_in[13];
    const float* gb_hh  = (const float*)d_in[14];
    const float* lin1_w = (const float*)d_in[15];
    const float* lin1_b = (const float*)d_in[16];
    const float* lin2_w = (const float*)d_in[17];
    const float* lin2_b = (const float*)d_in[18];

    const int n = in_sizes[0] / 16;   // 100000
    const int e = in_sizes[2] / 5;    // 200000
    const int* src = ei;
    const int* dst = ei + e;

    cudaFuncSetAttribute(k_we, cudaFuncAttributeMaxDynamicSharedMemorySize, WE_SMEM_BYTES);

    k_init<<<1024, 256>>>(n);
    k_count<<<(e + 255) / 256, 256>>>(dst, e);
    k_lin0<<<(n * 32 + 255) / 256, 256>>>(x, lin0_w, lin0_b, n);

    dim3 wgrid(8, (e + 127) / 128);
    k_we<<<wgrid, 256, WE_SMEM_BYTES>>>(ea, mlp_w1, mlp_b1, mlp_w2, mlp_b2, e);

    for (int it = 0; it < 3; it++) {
        k_msg<<<(e * 32 + 255) / 256, 256>>>(src, dst, e);
        k_update<<<(n * 32 + 511) / 512, 512>>>(root_w, conv_b, gw_ih, gw_hh, gb_ih, gb_hh, n);
    }

    k_final<<<(n * 32 + 255) / 256, 256>>>(lin1_w, lin1_b, lin2_w, lin2_b, (float*)d_out, n);
}

// round 6
// speedup vs baseline: 1.1941x; 1.0048x over previous
#include <cuda_runtime.h>
#include <cuda_fp16.h>

// Problem constants
#define MAXN 100000
#define MAXE 200000

// -------- scratch (static device globals; no allocation) --------
// w_e stored fp16, TRANSPOSED per edge: g_weh[e][o][i] at offset e*1024 + o*32 + i
__device__ __half g_weh[(size_t)MAXE * 1024];   // 409.6 MB
__device__ float g_out[MAXN * 32];              // current node state
__device__ float g_agg[MAXN * 32];              // scatter accumulator
__device__ float g_cnt[MAXN];                   // in-degree counts

// -------- packed f32x2 helpers --------
__device__ __forceinline__ unsigned long long pack2(float lo, float hi) {
    unsigned long long r;
    asm("mov.b64 %0, {%1, %2};" : "=l"(r) : "f"(lo), "f"(hi));
    return r;
}
__device__ __forceinline__ void fma2(unsigned long long& d, unsigned long long a, unsigned long long b) {
    asm("fma.rn.f32x2 %0, %1, %2, %0;" : "+l"(d) : "l"(a), "l"(b));
}
__device__ __forceinline__ float2 unpack2(unsigned long long v) {
    float lo, hi;
    asm("mov.b64 {%0, %1}, %2;" : "=f"(lo), "=f"(hi) : "l"(v));
    return make_float2(lo, hi);
}

// ============================================================
// init: zero agg + cnt
// ============================================================
__global__ void k_init(int n) {
    int t = blockIdx.x * blockDim.x + threadIdx.x;
    int stride = gridDim.x * blockDim.x;
    for (int i = t; i < n * 32; i += stride) g_agg[i] = 0.f;
    for (int i = t; i < n; i += stride) g_cnt[i] = 0.f;
}

__global__ void k_count(const int* __restrict__ dst, int e) {
    int t = blockIdx.x * blockDim.x + threadIdx.x;
    if (t < e) atomicAdd(&g_cnt[dst[t]], 1.f);
}

// ============================================================
// lin0: out = relu(x @ lin0_w^T + b)   [N,16] -> [N,32]
// ============================================================
__global__ void k_lin0(const float* __restrict__ x, const float* __restrict__ w,
                       const float* __restrict__ b, int n) {
    __shared__ float wT[16 * 32];
    __shared__ float bs[32];
    int t = threadIdx.x;
    for (int i = t; i < 512; i += blockDim.x) {
        int d = i >> 4, k = i & 15;
        wT[k * 32 + d] = w[i];
    }
    if (t < 32) bs[t] = b[t];
    __syncthreads();

    int warp = (blockIdx.x * blockDim.x + t) >> 5;
    int lane = t & 31;
    if (warp >= n) return;
    float xk = (lane < 16) ? x[(size_t)warp * 16 + lane] : 0.f;
    float acc = bs[lane];
#pragma unroll
    for (int k = 0; k < 16; k++) {
        float xv = __shfl_sync(0xffffffffu, xk, k);
        acc = fmaf(wT[k * 32 + lane], xv, acc);
    }
    g_out[(size_t)warp * 32 + lane] = fmaxf(acc, 0.f);
}

// ============================================================
// w_e GEMM (fp16 output, per-edge transposed layout):
//   g_weh[e][c'] where c' = o*32+i, value = b2[i*32+o] + sum_h r[e,h]*W2[i*32+o, h]
// Transpose is free: the W2 smem staging reads permuted rows.
// Tile: 128 edges x 128 cols, K chunked 2x64 (smem ~67KB -> 2 blocks/SM).
// Per thread: 8 edges x 8 cols (4 f32x2 col-pairs), f32x2 FMA.
// Inner loop: manual register double-buffer (prefetch k+1 while FMAing k).
// ============================================================
#define WE_SMEM_BYTES ((64 * 128 + 64 * 132) * 4)

__global__ __launch_bounds__(256, 2) void k_we(
    const float* __restrict__ ea, const float* __restrict__ w1,
    const float* __restrict__ b1, const float* __restrict__ w2,
    const float* __restrict__ b2, int E)
{
    extern __shared__ float sm[];
    float* rT  = sm;              // [hh][el], 64 x 128
    float* w2T = sm + 64 * 128;   // [k][c],  64 x 132 (pad 132 keeps 16B align)
    __shared__ float eas[128 * 5];

    const int t = threadIdx.x;
    const int ebase = blockIdx.y * 128;
    const int cbase = blockIdx.x * 128;
    const int tx = t & 15;
    const int ty = t >> 4;

    // stage edge_attr tile (once)
    for (int i = t; i < 640; i += 256) {
        int el = i / 5, j = i - el * 5;
        int ge = ebase + el;
        eas[i] = (ge < E) ? ea[(size_t)ge * 5 + j] : 0.f;
    }

    unsigned long long acc[8][4];
#pragma unroll
    for (int i = 0; i < 8; i++)
#pragma unroll
        for (int j = 0; j < 4; j++) acc[i][j] = 0ull;

    for (int kc = 0; kc < 2; kc++) {
        __syncthreads();  // kc=0: orders eas; kc=1: protects smem reuse
        // merged staging: W2 chunk (permuted transpose) + hidden r chunk
        for (int i = t; i < 8192; i += 256) {
            // W2: local col c, k
            {
                int c = i >> 6, k = i & 63;
                int cg = cbase + c;
                int sr = ((cg & 31) << 5) | (cg >> 5);
                w2T[k * 132 + c] = __ldg(&w2[(size_t)sr * 128 + kc * 64 + k]);
            }
            // r: edge el, hidden hh
            {
                int el = i & 127, hh = i >> 7;
                int h = kc * 64 + hh;
                float a = __ldg(&b1[h]);
#pragma unroll
                for (int j = 0; j < 5; j++)
                    a = fmaf(eas[el * 5 + j], __ldg(&w1[h * 5 + j]), a);
                rT[hh * 128 + el] = fmaxf(a, 0.f);
            }
        }
        __syncthreads();

        // ---- inner loop: register double-buffered over kk ----
        const float* rbase = &rT[ty * 8];
        const float* wbase = &w2T[4 * tx];

        float4 a0c = *(const float4*)(rbase);
        float4 a1c = *(const float4*)(rbase + 4);
        ulonglong2 b0c = *(const ulonglong2*)(wbase);
        ulonglong2 b1c = *(const ulonglong2*)(wbase + 64);

#pragma unroll
        for (int kk = 0; kk < 64; kk++) {
            float4 a0n, a1n;
            ulonglong2 b0n, b1n;
            if (kk < 63) {
                const float* rn = rbase + (kk + 1) * 128;
                const float* wn = wbase + (kk + 1) * 132;
                a0n = *(const float4*)(rn);
                a1n = *(const float4*)(rn + 4);
                b0n = *(const ulonglong2*)(wn);
                b1n = *(const ulonglong2*)(wn + 64);
            }
            unsigned long long A[8];
            A[0] = pack2(a0c.x, a0c.x); A[1] = pack2(a0c.y, a0c.y);
            A[2] = pack2(a0c.z, a0c.z); A[3] = pack2(a0c.w, a0c.w);
            A[4] = pack2(a1c.x, a1c.x); A[5] = pack2(a1c.y, a1c.y);
            A[6] = pack2(a1c.z, a1c.z); A[7] = pack2(a1c.w, a1c.w);
#pragma unroll
            for (int i = 0; i < 8; i++) {
                fma2(acc[i][0], A[i], b0c.x);
                fma2(acc[i][1], A[i], b0c.y);
                fma2(acc[i][2], A[i], b1c.x);
                fma2(acc[i][3], A[i], b1c.y);
            }
            if (kk < 63) { a0c = a0n; a1c = a1n; b0c = b0n; b1c = b1n; }
        }
    }

    // epilogue: add permuted b2, convert to fp16, store 8B per quad
    float bias[8];
#pragma unroll
    for (int j = 0; j < 8; j++) {
        int c = (j < 4) ? (4 * tx + j) : (64 + 4 * tx + (j - 4));
        int cg = cbase + c;
        int sr = ((cg & 31) << 5) | (cg >> 5);
        bias[j] = __ldg(&b2[sr]);
    }
#pragma unroll
    for (int i = 0; i < 8; i++) {
        int ge = ebase + ty * 8 + i;
        if (ge >= E) continue;
        __half* dp = &g_weh[(size_t)ge * 1024 + cbase];
        float2 v0 = unpack2(acc[i][0]), v1 = unpack2(acc[i][1]);
        float2 v2 = unpack2(acc[i][2]), v3 = unpack2(acc[i][3]);
        union { __half2 h[2]; uint2 u; } q0, q1;
        q0.h[0] = __floats2half2_rn(v0.x + bias[0], v0.y + bias[1]);
        q0.h[1] = __floats2half2_rn(v1.x + bias[2], v1.y + bias[3]);
        q1.h[0] = __floats2half2_rn(v2.x + bias[4], v2.y + bias[5]);
        q1.h[1] = __floats2half2_rn(v3.x + bias[6], v3.y + bias[7]);
        *(uint2*)(dp + 4 * tx) = q0.u;
        *(uint2*)(dp + 64 + 4 * tx) = q1.u;
    }
}

// ============================================================
// message pass: msg[e,o] = sum_i out[src[e]][i] * w_t[e][o][i]
// Warp per edge, lane = o. Lane-private 64B (4x LDG.128) -> dot product.
// ============================================================
__global__ void k_msg(const int* __restrict__ src, const int* __restrict__ dst, int e) {
    int warp = (blockIdx.x * blockDim.x + threadIdx.x) >> 5;
    int lane = threadIdx.x & 31;
    if (warp >= e) return;
    int s = __ldg(&src[warp]);
    int d = __ldg(&dst[warp]);
    const uint4* wp = (const uint4*)(g_weh + (size_t)warp * 1024 + lane * 32);
    uint4 w0 = __ldg(&wp[0]);
    uint4 w1 = __ldg(&wp[1]);
    uint4 w2 = __ldg(&wp[2]);
    uint4 w3 = __ldg(&wp[3]);
    float sv = g_out[(size_t)s * 32 + lane];
    float acc = 0.f;

#define ACC2(u, i0) do { \
        float2 f_ = __half22float2(*(const __half2*)&(u)); \
        acc = fmaf(__shfl_sync(0xffffffffu, sv, (i0)), f_.x, acc); \
        acc = fmaf(__shfl_sync(0xffffffffu, sv, (i0) + 1), f_.y, acc); \
    } while (0)

    ACC2(w0.x, 0);  ACC2(w0.y, 2);  ACC2(w0.z, 4);  ACC2(w0.w, 6);
    ACC2(w1.x, 8);  ACC2(w1.y, 10); ACC2(w1.z, 12); ACC2(w1.w, 14);
    ACC2(w2.x, 16); ACC2(w2.y, 18); ACC2(w2.z, 20); ACC2(w2.w, 22);
    ACC2(w3.x, 24); ACC2(w3.y, 26); ACC2(w3.z, 28); ACC2(w3.w, 30);
#undef ACC2

    atomicAdd(&g_agg[(size_t)d * 32 + lane], acc);
}

// ============================================================
// fused NNConv-root + GRU update (warp per node), re-zeros agg
// ============================================================
__global__ void k_update(const float* __restrict__ root_w, const float* __restrict__ conv_b,
                         const float* __restrict__ wih, const float* __restrict__ whh,
                         const float* __restrict__ bih, const float* __restrict__ bhh, int n) {
    __shared__ float rootT[32 * 33];
    __shared__ float wihT[32 * 97];
    __shared__ float whhT[32 * 97];
    __shared__ float cb[32], bi[96], bh[96];
    int t = threadIdx.x;
    for (int i = t; i < 1024; i += blockDim.x) {
        int d = i >> 5, j = i & 31;
        rootT[j * 33 + d] = root_w[i];
    }
    for (int i = t; i < 3072; i += blockDim.x) {
        int rr = i >> 5, j = i & 31;
        wihT[j * 97 + rr] = wih[i];
        whhT[j * 97 + rr] = whh[i];
    }
    if (t < 32) cb[t] = conv_b[t];
    if (t < 96) { bi[t] = bih[t]; bh[t] = bhh[t]; }
    __syncthreads();

    int warp = (blockIdx.x * blockDim.x + t) >> 5;
    int lane = t & 31;
    if (warp >= n) return;
    size_t base = (size_t)warp * 32 + lane;

    float h = g_out[base];
    float c = fmaxf(g_cnt[warp], 1.f);
    float m = g_agg[base] / c + cb[lane];
#pragma unroll
    for (int j = 0; j < 32; j++) {
        float hj = __shfl_sync(0xffffffffu, h, j);
        m = fmaf(rootT[j * 33 + lane], hj, m);
    }
    m = fmaxf(m, 0.f);

    float gr = bi[lane], gz = bi[32 + lane], gn = bi[64 + lane];
    float hr = bh[lane], hz = bh[32 + lane], hn = bh[64 + lane];
#pragma unroll
    for (int j = 0; j < 32; j++) {
        float mj = __shfl_sync(0xffffffffu, m, j);
        float hj = __shfl_sync(0xffffffffu, h, j);
        gr = fmaf(wihT[j * 97 + lane], mj, gr);
        gz = fmaf(wihT[j * 97 + 32 + lane], mj, gz);
        gn = fmaf(wihT[j * 97 + 64 + lane], mj, gn);
        hr = fmaf(whhT[j * 97 + lane], hj, hr);
        hz = fmaf(whhT[j * 97 + 32 + lane], hj, hz);
        hn = fmaf(whhT[j * 97 + 64 + lane], hj, hn);
    }
    float r = 1.f / (1.f + __expf(-(gr + hr)));
    float z = 1.f / (1.f + __expf(-(gz + hz)));
    float nn = tanhf(gn + r * hn);
    float hnew = (1.f - z) * nn + z * h;

    g_out[base] = hnew;
    g_agg[base] = 0.f;
}

// ============================================================
// final: y = relu(out @ lin1^T + b1) @ lin2^T + b2   -> [N,1]
// ============================================================
__global__ void k_final(const float* __restrict__ l1w, const float* __restrict__ l1b,
                        const float* __restrict__ l2w, const float* __restrict__ l2b,
                        float* __restrict__ out, int n) {
    __shared__ float w1T[32 * 33];
    __shared__ float b1s[32], w2s[32];
    int t = threadIdx.x;
    for (int i = t; i < 1024; i += blockDim.x) {
        int d = i >> 5, j = i & 31;
        w1T[j * 33 + d] = l1w[i];
    }
    if (t < 32) { b1s[t] = l1b[t]; w2s[t] = l2w[t]; }
    __syncthreads();

    int warp = (blockIdx.x * blockDim.x + t) >> 5;
    int lane = t & 31;
    if (warp >= n) return;
    float h = g_out[(size_t)warp * 32 + lane];
    float acc = b1s[lane];
#pragma unroll
    for (int j = 0; j < 32; j++) {
        float hj = __shfl_sync(0xffffffffu, h, j);
        acc = fmaf(w1T[j * 33 + lane], hj, acc);
    }
    acc = fmaxf(acc, 0.f);
    float p = acc * w2s[lane];
#pragma unroll
    for (int off = 16; off; off >>= 1) p += __shfl_xor_sync(0xffffffffu, p, off);
    if (lane == 0) out[warp] = p + __ldg(&l2b[0]);
}

// ============================================================
// launcher
// ============================================================
extern "C" void kernel_launch(void* const* d_in, const int* in_sizes, int n_in,
                              void* d_out, int out_size) {
    const float* x      = (const float*)d_in[0];
    const int*   ei     = (const int*)  d_in[1];
    const float* ea     = (const float*)d_in[2];
    const float* lin0_w = (const float*)d_in[3];
    const float* lin0_b = (const float*)d_in[4];
    const float* mlp_w1 = (const float*)d_in[5];
    const float* mlp_b1 = (const float*)d_in[6];
    const float* mlp_w2 = (const float*)d_in[7];
    const float* mlp_b2 = (const float*)d_in[8];
    const float* root_w = (const float*)d_in[9];
    const float* conv_b = (const float*)d_in[10];
    const float* gw_ih  = (const float*)d_in[11];
    const float* gw_hh  = (const float*)d_in[12];
    const float* gb_ih  = (const float*)d_in[13];
    const float* gb_hh  = (const float*)d_in[14];
    const float* lin1_w = (const float*)d_in[15];
    const float* lin1_b = (const float*)d_in[16];
    const float* lin2_w = (const float*)d_in[17];
    const float* lin2_b = (const float*)d_in[18];

    const int n = in_sizes[0] / 16;   // 100000
    const int e = in_sizes[2] / 5;    // 200000
    const int* src = ei;
    const int* dst = ei + e;

    cudaFuncSetAttribute(k_we, cudaFuncAttributeMaxDynamicSharedMemorySize, WE_SMEM_BYTES);

    k_init<<<1024, 256>>>(n);
    k_count<<<(e + 255) / 256, 256>>>(dst, e);
    k_lin0<<<(n * 32 + 255) / 256, 256>>>(x, lin0_w, lin0_b, n);

    dim3 wgrid(8, (e + 127) / 128);
    k_we<<<wgrid, 256, WE_SMEM_BYTES>>>(ea, mlp_w1, mlp_b1, mlp_w2, mlp_b2, e);

    for (int it = 0; it < 3; it++) {
        k_msg<<<(e * 32 + 255) / 256, 256>>>(src, dst, e);
        k_update<<<(n * 32 + 511) / 512, 512>>>(root_w, conv_b, gw_ih, gw_hh, gb_ih, gb_hh, n);
    }

    k_final<<<(n * 32 + 255) / 256, 256>>>(lin1_w, lin1_b, lin2_w, lin2_b, (float*)d_out, n);
}

// round 7
// speedup vs baseline: 2.0138x; 1.6864x over previous
#include <cuda_runtime.h>
#include <cuda_fp16.h>
#include <cstdint>

// Problem constants
#define MAXN 100000
#define MAXE 200000

// -------- scratch (static device globals; no allocation) --------
// w_e stored fp16, TRANSPOSED per edge: g_weh[e][o][i] at flat col n = o*32+i
__device__ __half g_weh[(size_t)MAXE * 1024];   // 409.6 MB
__device__ __half g_w2h[1024 * 128];            // fp16 W2, rows PERMUTED by sr(n)
__device__ float g_out[MAXN * 32];
__device__ float g_agg[MAXN * 32];
__device__ float g_cnt[MAXN];

__device__ __forceinline__ uint32_t smem_u32(const void* p) {
    uint32_t a;
    asm("{ .reg .u64 t; cvta.to.shared.u64 t, %1; cvt.u32.u64 %0, t; }" : "=r"(a) : "l"(p));
    return a;
}
__device__ __forceinline__ void ldsm_x4(uint32_t& r0, uint32_t& r1, uint32_t& r2, uint32_t& r3,
                                        uint32_t addr) {
    asm volatile("ldmatrix.sync.aligned.m8n8.x4.shared.b16 {%0,%1,%2,%3}, [%4];"
        : "=r"(r0), "=r"(r1), "=r"(r2), "=r"(r3) : "r"(addr));
}
__device__ __forceinline__ void mma16816(float* d, const uint32_t* a, const uint32_t* b) {
    asm volatile("mma.sync.aligned.m16n8k16.row.col.f32.f16.f16.f32 "
        "{%0,%1,%2,%3}, {%4,%5,%6,%7}, {%8,%9}, {%0,%1,%2,%3};"
        : "+f"(d[0]), "+f"(d[1]), "+f"(d[2]), "+f"(d[3])
        : "r"(a[0]), "r"(a[1]), "r"(a[2]), "r"(a[3]), "r"(b[0]), "r"(b[1]));
}

// ============================================================
// prep: W2 fp32 [1024,128] -> fp16, rows permuted by sr(n)
// ============================================================
__global__ void k_prep(const float* __restrict__ w2) {
    int i = blockIdx.x * blockDim.x + threadIdx.x;
    if (i >= 1024 * 128) return;
    int n = i >> 7, k = i & 127;
    int sr = ((n & 31) << 5) | (n >> 5);
    g_w2h[n * 128 + k] = __float2half(w2[(size_t)sr * 128 + k]);
}

// ============================================================
// init / count / lin0
// ============================================================
__global__ void k_init(int n) {
    int t = blockIdx.x * blockDim.x + threadIdx.x;
    int stride = gridDim.x * blockDim.x;
    for (int i = t; i < n * 32; i += stride) g_agg[i] = 0.f;
    for (int i = t; i < n; i += stride) g_cnt[i] = 0.f;
}
__global__ void k_count(const int* __restrict__ dst, int e) {
    int t = blockIdx.x * blockDim.x + threadIdx.x;
    if (t < e) atomicAdd(&g_cnt[dst[t]], 1.f);
}
__global__ void k_lin0(const float* __restrict__ x, const float* __restrict__ w,
                       const float* __restrict__ b, int n) {
    __shared__ float wT[16 * 32];
    __shared__ float bs[32];
    int t = threadIdx.x;
    for (int i = t; i < 512; i += blockDim.x) {
        int d = i >> 4, k = i & 15;
        wT[k * 32 + d] = w[i];
    }
    if (t < 32) bs[t] = b[t];
    __syncthreads();
    int warp = (blockIdx.x * blockDim.x + t) >> 5;
    int lane = t & 31;
    if (warp >= n) return;
    float xk = (lane < 16) ? x[(size_t)warp * 16 + lane] : 0.f;
    float acc = bs[lane];
#pragma unroll
    for (int k = 0; k < 16; k++) {
        float xv = __shfl_sync(0xffffffffu, xk, k);
        acc = fmaf(wT[k * 32 + lane], xv, acc);
    }
    g_out[(size_t)warp * 32 + lane] = fmaxf(acc, 0.f);
}

// ============================================================
// w_e GEMM via mma.sync (fallback-HMMA tensor path, fp16 in / fp32 acc):
//   D[e, n] = sum_k r[e,k] * g_w2h[n][k]   (n pre-permuted so output = [o][i])
// Tile: 128 edges x 128 cols, K=128. 8 warps, each 32(M) x 64(N).
// A/B in smem, 136-half row stride -> conflict-free ldmatrix, 16B aligned.
// ============================================================
#define STR_H 136
#define WE_SMEM_BYTES (2 * 128 * STR_H * 2)

__global__ __launch_bounds__(256, 2) void k_we(
    const float* __restrict__ ea, const float* __restrict__ w1,
    const float* __restrict__ b1, const float* __restrict__ b2, int E)
{
    extern __shared__ __half smh[];
    __half* Asm = smh;                   // [128 el][136 k]
    __half* Bsm = smh + 128 * STR_H;     // [128 n ][136 k]
    __shared__ float eas[128 * 5];
    __shared__ float bias_s[128];

    const int tid = threadIdx.x;
    const int w = tid >> 5;
    const int lane = tid & 31;
    const int ebase = blockIdx.y * 128;
    const int cbase = blockIdx.x * 128;

    // stage edge_attr
    for (int i = tid; i < 640; i += 256) {
        int el = i / 5, j = i - el * 5;
        int ge = ebase + el;
        eas[i] = (ge < E) ? ea[(size_t)ge * 5 + j] : 0.f;
    }
    if (tid < 128) {
        int cg = cbase + tid;
        int sr = ((cg & 31) << 5) | (cg >> 5);
        bias_s[tid] = __ldg(&b2[sr]);
    }
    __syncthreads();

    // compute r (edge MLP hidden) -> Asm fp16
    for (int i = tid; i < 16384; i += 256) {
        int el = i >> 7, h = i & 127;
        float a = __ldg(&b1[h]);
        const float* e5 = &eas[el * 5];
#pragma unroll
        for (int j = 0; j < 5; j++)
            a = fmaf(e5[j], __ldg(&w1[h * 5 + j]), a);
        Asm[el * STR_H + h] = __float2half(fmaxf(a, 0.f));
    }
    // stage B (already fp16, permuted) -> Bsm
    for (int i = tid; i < 2048; i += 256) {
        int n = i >> 4, k0 = (i & 15) * 8;
        *(uint4*)&Bsm[n * STR_H + k0] = *(const uint4*)(g_w2h + (size_t)(cbase + n) * 128 + k0);
    }
    __syncthreads();

    const uint32_t Abase = smem_u32(Asm);
    const uint32_t Bbase = smem_u32(Bsm);
    const int R = (w & 3) * 32;      // warp M offset
    const int C = (w >> 2) * 64;     // warp N offset
    const int lt = lane >> 3;        // ldmatrix tile quad
    const int lr = lane & 7;

    float acc[2][8][4];
#pragma unroll
    for (int rt = 0; rt < 2; rt++)
#pragma unroll
        for (int nt = 0; nt < 8; nt++)
#pragma unroll
            for (int q = 0; q < 4; q++) acc[rt][nt][q] = 0.f;

#pragma unroll
    for (int ks = 0; ks < 8; ks++) {
        // A fragments: tiles {rows0-7 k0-7, rows8-15 k0-7, rows0-7 k8-15, rows8-15 k8-15}
        uint32_t a[2][4];
#pragma unroll
        for (int rt = 0; rt < 2; rt++) {
            int row = R + rt * 16 + (lt & 1) * 8 + lr;
            int kseg = lt >> 1;
            ldsm_x4(a[rt][0], a[rt][1], a[rt][2], a[rt][3],
                    Abase + (row * STR_H + ks * 16 + kseg * 8) * 2);
        }
        // B fragments: tiles {n0-7 k0-7, n0-7 k8-15, n8-15 k0-7, n8-15 k8-15}
        uint32_t b[8][2];
#pragma unroll
        for (int np = 0; np < 4; np++) {
            int n = C + np * 16 + (lt >> 1) * 8 + lr;
            int kseg = lt & 1;
            uint32_t r0, r1, r2, r3;
            ldsm_x4(r0, r1, r2, r3, Bbase + (n * STR_H + ks * 16 + kseg * 8) * 2);
            b[2 * np][0] = r0; b[2 * np][1] = r1;
            b[2 * np + 1][0] = r2; b[2 * np + 1][1] = r3;
        }
#pragma unroll
        for (int rt = 0; rt < 2; rt++)
#pragma unroll
            for (int nt = 0; nt < 8; nt++)
                mma16816(acc[rt][nt], a[rt], b[nt]);
    }

    // epilogue: +bias, fp16, store
    const int qr = lane >> 2, qc = (lane & 3) * 2;
#pragma unroll
    for (int rt = 0; rt < 2; rt++) {
#pragma unroll
        for (int h8 = 0; h8 < 2; h8++) {
            int ge = ebase + R + rt * 16 + h8 * 8 + qr;
            if (ge >= E) continue;
            __half* dp = &g_weh[(size_t)ge * 1024 + cbase + C];
#pragma unroll
            for (int nt = 0; nt < 8; nt++) {
                int c = nt * 8 + qc;
                float d0 = acc[rt][nt][h8 * 2 + 0];
                float d1 = acc[rt][nt][h8 * 2 + 1];
                *(__half2*)(dp + c) =
                    __floats2half2_rn(d0 + bias_s[C + c], d1 + bias_s[C + c + 1]);
            }
        }
    }
}

// ============================================================
// message pass: lane-private coalesced fp16 reads (unchanged)
// ============================================================
__global__ void k_msg(const int* __restrict__ src, const int* __restrict__ dst, int e) {
    int warp = (blockIdx.x * blockDim.x + threadIdx.x) >> 5;
    int lane = threadIdx.x & 31;
    if (warp >= e) return;
    int s = __ldg(&src[warp]);
    int d = __ldg(&dst[warp]);
    const uint4* wp = (const uint4*)(g_weh + (size_t)warp * 1024 + lane * 32);
    uint4 w0 = __ldg(&wp[0]);
    uint4 w1 = __ldg(&wp[1]);
    uint4 w2 = __ldg(&wp[2]);
    uint4 w3 = __ldg(&wp[3]);
    float sv = g_out[(size_t)s * 32 + lane];
    float acc = 0.f;
#define ACC2(u, i0) do { \
        float2 f_ = __half22float2(*(const __half2*)&(u)); \
        acc = fmaf(__shfl_sync(0xffffffffu, sv, (i0)), f_.x, acc); \
        acc = fmaf(__shfl_sync(0xffffffffu, sv, (i0) + 1), f_.y, acc); \
    } while (0)
    ACC2(w0.x, 0);  ACC2(w0.y, 2);  ACC2(w0.z, 4);  ACC2(w0.w, 6);
    ACC2(w1.x, 8);  ACC2(w1.y, 10); ACC2(w1.z, 12); ACC2(w1.w, 14);
    ACC2(w2.x, 16); ACC2(w2.y, 18); ACC2(w2.z, 20); ACC2(w2.w, 22);
    ACC2(w3.x, 24); ACC2(w3.y, 26); ACC2(w3.z, 28); ACC2(w3.w, 30);
#undef ACC2
    atomicAdd(&g_agg[(size_t)d * 32 + lane], acc);
}

// ============================================================
// fused NNConv-root + GRU update (unchanged)
// ============================================================
__global__ void k_update(const float* __restrict__ root_w, const float* __restrict__ conv_b,
                         const float* __restrict__ wih, const float* __restrict__ whh,
                         const float* __restrict__ bih, const float* __restrict__ bhh, int n) {
    __shared__ float rootT[32 * 33];
    __shared__ float wihT[32 * 97];
    __shared__ float whhT[32 * 97];
    __shared__ float cb[32], bi[96], bh[96];
    int t = threadIdx.x;
    for (int i = t; i < 1024; i += blockDim.x) {
        int d = i >> 5, j = i & 31;
        rootT[j * 33 + d] = root_w[i];
    }
    for (int i = t; i < 3072; i += blockDim.x) {
        int rr = i >> 5, j = i & 31;
        wihT[j * 97 + rr] = wih[i];
        whhT[j * 97 + rr] = whh[i];
    }
    if (t < 32) cb[t] = conv_b[t];
    if (t < 96) { bi[t] = bih[t]; bh[t] = bhh[t]; }
    __syncthreads();

    int warp = (blockIdx.x * blockDim.x + t) >> 5;
    int lane = t & 31;
    if (warp >= n) return;
    size_t base = (size_t)warp * 32 + lane;

    float h = g_out[base];
    float c = fmaxf(g_cnt[warp], 1.f);
    float m = g_agg[base] / c + cb[lane];
#pragma unroll
    for (int j = 0; j < 32; j++) {
        float hj = __shfl_sync(0xffffffffu, h, j);
        m = fmaf(rootT[j * 33 + lane], hj, m);
    }
    m = fmaxf(m, 0.f);

    float gr = bi[lane], gz = bi[32 + lane], gn = bi[64 + lane];
    float hr = bh[lane], hz = bh[32 + lane], hn = bh[64 + lane];
#pragma unroll
    for (int j = 0; j < 32; j++) {
        float mj = __shfl_sync(0xffffffffu, m, j);
        float hj = __shfl_sync(0xffffffffu, h, j);
        gr = fmaf(wihT[j * 97 + lane], mj, gr);
        gz = fmaf(wihT[j * 97 + 32 + lane], mj, gz);
        gn = fmaf(wihT[j * 97 + 64 + lane], mj, gn);
        hr = fmaf(whhT[j * 97 + lane], hj, hr);
        hz = fmaf(whhT[j * 97 + 32 + lane], hj, hz);
        hn = fmaf(whhT[j * 97 + 64 + lane], hj, hn);
    }
    float r = 1.f / (1.f + __expf(-(gr + hr)));
    float z = 1.f / (1.f + __expf(-(gz + hz)));
    float nn = tanhf(gn + r * hn);
    float hnew = (1.f - z) * nn + z * h;

    g_out[base] = hnew;
    g_agg[base] = 0.f;
}

// ============================================================
// final readout (unchanged)
// ============================================================
__global__ void k_final(const float* __restrict__ l1w, const float* __restrict__ l1b,
                        const float* __restrict__ l2w, const float* __restrict__ l2b,
                        float* __restrict__ out, int n) {
    __shared__ float w1T[32 * 33];
    __shared__ float b1s[32], w2s[32];
    int t = threadIdx.x;
    for (int i = t; i < 1024; i += blockDim.x) {
        int d = i >> 5, j = i & 31;
        w1T[j * 33 + d] = l1w[i];
    }
    if (t < 32) { b1s[t] = l1b[t]; w2s[t] = l2w[t]; }
    __syncthreads();

    int warp = (blockIdx.x * blockDim.x + t) >> 5;
    int lane = t & 31;
    if (warp >= n) return;
    float h = g_out[(size_t)warp * 32 + lane];
    float acc = b1s[lane];
#pragma unroll
    for (int j = 0; j < 32; j++) {
        float hj = __shfl_sync(0xffffffffu, h, j);
        acc = fmaf(w1T[j * 33 + lane], hj, acc);
    }
    acc = fmaxf(acc, 0.f);
    float p = acc * w2s[lane];
#pragma unroll
    for (int off = 16; off; off >>= 1) p += __shfl_xor_sync(0xffffffffu, p, off);
    if (lane == 0) out[warp] = p + __ldg(&l2b[0]);
}

// ============================================================
// launcher
// ============================================================
extern "C" void kernel_launch(void* const* d_in, const int* in_sizes, int n_in,
                              void* d_out, int out_size) {
    const float* x      = (const float*)d_in[0];
    const int*   ei     = (const int*)  d_in[1];
    const float* ea     = (const float*)d_in[2];
    const float* lin0_w = (const float*)d_in[3];
    const float* lin0_b = (const float*)d_in[4];
    const float* mlp_w1 = (const float*)d_in[5];
    const float* mlp_b1 = (const float*)d_in[6];
    const float* mlp_w2 = (const float*)d_in[7];
    const float* mlp_b2 = (const float*)d_in[8];
    const float* root_w = (const float*)d_in[9];
    const float* conv_b = (const float*)d_in[10];
    const float* gw_ih  = (const float*)d_in[11];
    const float* gw_hh  = (const float*)d_in[12];
    const float* gb_ih  = (const float*)d_in[13];
    const float* gb_hh  = (const float*)d_in[14];
    const float* lin1_w = (const float*)d_in[15];
    const float* lin1_b = (const float*)d_in[16];
    const float* lin2_w = (const float*)d_in[17];
    const float* lin2_b = (const float*)d_in[18];

    const int n = in_sizes[0] / 16;   // 100000
    const int e = in_sizes[2] / 5;    // 200000
    const int* src = ei;
    const int* dst = ei + e;

    cudaFuncSetAttribute(k_we, cudaFuncAttributeMaxDynamicSharedMemorySize, WE_SMEM_BYTES);

    k_init<<<1024, 256>>>(n);
    k_count<<<(e + 255) / 256, 256>>>(dst, e);
    k_lin0<<<(n * 32 + 255) / 256, 256>>>(x, lin0_w, lin0_b, n);
    k_prep<<<(1024 * 128 + 255) / 256, 256>>>(mlp_w2);

    dim3 wgrid(8, (e + 127) / 128);
    k_we<<<wgrid, 256, WE_SMEM_BYTES>>>(ea, mlp_w1, mlp_b1, mlp_b2, e);

    for (int it = 0; it < 3; it++) {
        k_msg<<<(e * 32 + 255) / 256, 256>>>(src, dst, e);
        k_update<<<(n * 32 + 511) / 512, 512>>>(root_w, conv_b, gw_ih, gw_hh, gb_ih, gb_hh, n);
    }

    k_final<<<(n * 32 + 255) / 256, 256>>>(lin1_w, lin1_b, lin2_w, lin2_b, (float*)d_out, n);
}

// round 8
// speedup vs baseline: 2.4043x; 1.1940x over previous
#include <cuda_runtime.h>
#include <cuda_fp16.h>
#include <cstdint>

// Problem constants
#define MAXN 100000
#define MAXE 200000

// -------- scratch (static device globals; no allocation) --------
// w_e stored fp16, TRANSPOSED per edge: g_weh[e][o][i] at flat col n = o*32+i
__device__ __half g_weh[(size_t)MAXE * 1024];   // 409.6 MB
__device__ __half g_w2h[1024 * 128];            // fp16 W2, rows PERMUTED by sr(n)
__device__ float g_b2p[1024];                   // permuted b2
__device__ float g_out[MAXN * 32];
__device__ float g_agg[MAXN * 32];
__device__ float g_cnt[MAXN];

__device__ __forceinline__ uint32_t smem_u32(const void* p) {
    uint32_t a;
    asm("{ .reg .u64 t; cvta.to.shared.u64 t, %1; cvt.u32.u64 %0, t; }" : "=r"(a) : "l"(p));
    return a;
}
__device__ __forceinline__ void ldsm_x4(uint32_t& r0, uint32_t& r1, uint32_t& r2, uint32_t& r3,
                                        uint32_t addr) {
    asm volatile("ldmatrix.sync.aligned.m8n8.x4.shared.b16 {%0,%1,%2,%3}, [%4];"
        : "=r"(r0), "=r"(r1), "=r"(r2), "=r"(r3) : "r"(addr));
}
__device__ __forceinline__ void mma16816(float* d, const uint32_t* a, const uint32_t* b) {
    asm volatile("mma.sync.aligned.m16n8k16.row.col.f32.f16.f16.f32 "
        "{%0,%1,%2,%3}, {%4,%5,%6,%7}, {%8,%9}, {%0,%1,%2,%3};"
        : "+f"(d[0]), "+f"(d[1]), "+f"(d[2]), "+f"(d[3])
        : "r"(a[0]), "r"(a[1]), "r"(a[2]), "r"(a[3]), "r"(b[0]), "r"(b[1]));
}
#define CP_ASYNC16(dst, src) \
    asm volatile("cp.async.cg.shared.global [%0], [%1], 16;" :: "r"(dst), "l"(src))
#define CP_COMMIT() asm volatile("cp.async.commit_group;")
#define CP_WAIT0()  asm volatile("cp.async.wait_group 0;")

// ============================================================
// prep: W2 fp32 [1024,128] -> fp16, rows permuted by sr(n); also permuted b2
// ============================================================
__global__ void k_prep(const float* __restrict__ w2, const float* __restrict__ b2) {
    int i = blockIdx.x * blockDim.x + threadIdx.x;
    if (i >= 1024 * 128) return;
    int n = i >> 7, k = i & 127;
    int sr = ((n & 31) << 5) | (n >> 5);
    g_w2h[n * 128 + k] = __float2half(w2[(size_t)sr * 128 + k]);
    if (k == 0) g_b2p[n] = b2[sr];
}

// ============================================================
// init / count / lin0
// ============================================================
__global__ void k_init(int n) {
    int t = blockIdx.x * blockDim.x + threadIdx.x;
    int stride = gridDim.x * blockDim.x;
    for (int i = t; i < n * 32; i += stride) g_agg[i] = 0.f;
    for (int i = t; i < n; i += stride) g_cnt[i] = 0.f;
}
__global__ void k_count(const int* __restrict__ dst, int e) {
    int t = blockIdx.x * blockDim.x + threadIdx.x;
    if (t < e) atomicAdd(&g_cnt[dst[t]], 1.f);
}
__global__ void k_lin0(const float* __restrict__ x, const float* __restrict__ w,
                       const float* __restrict__ b, int n) {
    __shared__ float wT[16 * 32];
    __shared__ float bs[32];
    int t = threadIdx.x;
    for (int i = t; i < 512; i += blockDim.x) {
        int d = i >> 4, k = i & 15;
        wT[k * 32 + d] = w[i];
    }
    if (t < 32) bs[t] = b[t];
    __syncthreads();
    int warp = (blockIdx.x * blockDim.x + t) >> 5;
    int lane = t & 31;
    if (warp >= n) return;
    float xk = (lane < 16) ? x[(size_t)warp * 16 + lane] : 0.f;
    float acc = bs[lane];
#pragma unroll
    for (int k = 0; k < 16; k++) {
        float xv = __shfl_sync(0xffffffffu, xk, k);
        acc = fmaf(wT[k * 32 + lane], xv, acc);
    }
    g_out[(size_t)warp * 32 + lane] = fmaxf(acc, 0.f);
}

// ============================================================
// w_e GEMM via mma.sync: one CTA = 128 edges x FULL 1024 cols, K=128.
// A (edge MLP hidden) computed ONCE per CTA; B streamed from L2 in 8
// 128-col chunks, double-buffered with cp.async. 8 warps: 32(M) x 64(N).
// ============================================================
#define STR_H 136
#define BUF_HALVES (128 * STR_H)
#define WE_SMEM_BYTES (3 * BUF_HALVES * 2)   // A + 2 B buffers

__global__ __launch_bounds__(256, 2) void k_we(
    const float* __restrict__ ea, const float* __restrict__ w1,
    const float* __restrict__ b1, int E)
{
    extern __shared__ __half smh[];
    __half* Asm = smh;                    // [128 el][136 k]
    __half* Bsm[2] = { smh + BUF_HALVES, smh + 2 * BUF_HALVES };
    __shared__ float eas[128 * 5];

    const int tid = threadIdx.x;
    const int w = tid >> 5;
    const int lane = tid & 31;
    const int ebase = blockIdx.x * 128;

    // prefetch B chunk 0 while we compute A
#define STAGE_B(chunk, buf) do { \
        const __half* gsrc = g_w2h + (size_t)(chunk) * 128 * 128; \
        for (int i = tid; i < 2048; i += 256) { \
            int n = i >> 4, k0 = (i & 15) * 8; \
            uint32_t dsa = smem_u32(&Bsm[buf][n * STR_H + k0]); \
            CP_ASYNC16(dsa, gsrc + n * 128 + k0); \
        } \
        CP_COMMIT(); \
    } while (0)

    STAGE_B(0, 0);

    // stage edge_attr
    for (int i = tid; i < 640; i += 256) {
        int el = i / 5, j = i - el * 5;
        int ge = ebase + el;
        eas[i] = (ge < E) ? ea[(size_t)ge * 5 + j] : 0.f;
    }
    __syncthreads();

    // compute r (edge MLP hidden) -> Asm fp16  (once per CTA)
    for (int i = tid; i < 16384; i += 256) {
        int el = i >> 7, h = i & 127;
        float a = __ldg(&b1[h]);
        const float* e5 = &eas[el * 5];
#pragma unroll
        for (int j = 0; j < 5; j++)
            a = fmaf(e5[j], __ldg(&w1[h * 5 + j]), a);
        Asm[el * STR_H + h] = __float2half(fmaxf(a, 0.f));
    }
    CP_WAIT0();
    __syncthreads();

    const uint32_t Abase = smem_u32(Asm);
    const int R = (w & 3) * 32;      // warp M offset
    const int C = (w >> 2) * 64;     // warp N offset within chunk
    const int lt = lane >> 3;
    const int lr = lane & 7;
    const int qr = lane >> 2, qc = (lane & 3) * 2;

    for (int chunk = 0; chunk < 8; chunk++) {
        const int cur = chunk & 1;
        const uint32_t Bbase = smem_u32(Bsm[cur]);
        // prefetch next chunk into the other buffer (safe: sync at end of prev iter)
        if (chunk < 7) STAGE_B(chunk + 1, cur ^ 1);

        float acc[2][8][4];
#pragma unroll
        for (int rt = 0; rt < 2; rt++)
#pragma unroll
            for (int nt = 0; nt < 8; nt++)
#pragma unroll
                for (int q = 0; q < 4; q++) acc[rt][nt][q] = 0.f;

#pragma unroll
        for (int ks = 0; ks < 8; ks++) {
            uint32_t a[2][4];
#pragma unroll
            for (int rt = 0; rt < 2; rt++) {
                int row = R + rt * 16 + (lt & 1) * 8 + lr;
                int kseg = lt >> 1;
                ldsm_x4(a[rt][0], a[rt][1], a[rt][2], a[rt][3],
                        Abase + (row * STR_H + ks * 16 + kseg * 8) * 2);
            }
            uint32_t b[8][2];
#pragma unroll
            for (int np = 0; np < 4; np++) {
                int n = C + np * 16 + (lt >> 1) * 8 + lr;
                int kseg = lt & 1;
                uint32_t r0, r1, r2, r3;
                ldsm_x4(r0, r1, r2, r3, Bbase + (n * STR_H + ks * 16 + kseg * 8) * 2);
                b[2 * np][0] = r0; b[2 * np][1] = r1;
                b[2 * np + 1][0] = r2; b[2 * np + 1][1] = r3;
            }
#pragma unroll
            for (int rt = 0; rt < 2; rt++)
#pragma unroll
                for (int nt = 0; nt < 8; nt++)
                    mma16816(acc[rt][nt], a[rt], b[nt]);
        }

        // epilogue: +bias, fp16, store
        const int colbase = chunk * 128 + C;
#pragma unroll
        for (int rt = 0; rt < 2; rt++) {
#pragma unroll
            for (int h8 = 0; h8 < 2; h8++) {
                int ge = ebase + R + rt * 16 + h8 * 8 + qr;
                if (ge >= E) continue;
                __half* dp = &g_weh[(size_t)ge * 1024 + colbase];
#pragma unroll
                for (int nt = 0; nt < 8; nt++) {
                    int c = nt * 8 + qc;
                    float d0 = acc[rt][nt][h8 * 2 + 0] + __ldg(&g_b2p[colbase + c]);
                    float d1 = acc[rt][nt][h8 * 2 + 1] + __ldg(&g_b2p[colbase + c + 1]);
                    *(__half2*)(dp + c) = __floats2half2_rn(d0, d1);
                }
            }
        }
        if (chunk < 7) {
            CP_WAIT0();
            __syncthreads();
        }
    }
#undef STAGE_B
}

// ============================================================
// message pass: lane-private coalesced fp16 streaming reads
// ============================================================
__global__ void k_msg(const int* __restrict__ src, const int* __restrict__ dst, int e) {
    int warp = (blockIdx.x * blockDim.x + threadIdx.x) >> 5;
    int lane = threadIdx.x & 31;
    if (warp >= e) return;
    int s = __ldg(&src[warp]);
    int d = __ldg(&dst[warp]);
    const uint4* wp = (const uint4*)(g_weh + (size_t)warp * 1024 + lane * 32);
    uint4 w0 = __ldcs(&wp[0]);
    uint4 w1 = __ldcs(&wp[1]);
    uint4 w2 = __ldcs(&wp[2]);
    uint4 w3 = __ldcs(&wp[3]);
    float sv = g_out[(size_t)s * 32 + lane];
    float acc = 0.f;
#define ACC2(u, i0) do { \
        float2 f_ = __half22float2(*(const __half2*)&(u)); \
        acc = fmaf(__shfl_sync(0xffffffffu, sv, (i0)), f_.x, acc); \
        acc = fmaf(__shfl_sync(0xffffffffu, sv, (i0) + 1), f_.y, acc); \
    } while (0)
    ACC2(w0.x, 0);  ACC2(w0.y, 2);  ACC2(w0.z, 4);  ACC2(w0.w, 6);
    ACC2(w1.x, 8);  ACC2(w1.y, 10); ACC2(w1.z, 12); ACC2(w1.w, 14);
    ACC2(w2.x, 16); ACC2(w2.y, 18); ACC2(w2.z, 20); ACC2(w2.w, 22);
    ACC2(w3.x, 24); ACC2(w3.y, 26); ACC2(w3.z, 28); ACC2(w3.w, 30);
#undef ACC2
    atomicAdd(&g_agg[(size_t)d * 32 + lane], acc);
}

// ============================================================
// fused NNConv-root + GRU update (unchanged)
// ============================================================
__global__ void k_update(const float* __restrict__ root_w, const float* __restrict__ conv_b,
                         const float* __restrict__ wih, const float* __restrict__ whh,
                         const float* __restrict__ bih, const float* __restrict__ bhh, int n) {
    __shared__ float rootT[32 * 33];
    __shared__ float wihT[32 * 97];
    __shared__ float whhT[32 * 97];
    __shared__ float cb[32], bi[96], bh[96];
    int t = threadIdx.x;
    for (int i = t; i < 1024; i += blockDim.x) {
        int d = i >> 5, j = i & 31;
        rootT[j * 33 + d] = root_w[i];
    }
    for (int i = t; i < 3072; i += blockDim.x) {
        int rr = i >> 5, j = i & 31;
        wihT[j * 97 + rr] = wih[i];
        whhT[j * 97 + rr] = whh[i];
    }
    if (t < 32) cb[t] = conv_b[t];
    if (t < 96) { bi[t] = bih[t]; bh[t] = bhh[t]; }
    __syncthreads();

    int warp = (blockIdx.x * blockDim.x + t) >> 5;
    int lane = t & 31;
    if (warp >= n) return;
    size_t base = (size_t)warp * 32 + lane;

    float h = g_out[base];
    float c = fmaxf(g_cnt[warp], 1.f);
    float m = g_agg[base] / c + cb[lane];
#pragma unroll
    for (int j = 0; j < 32; j++) {
        float hj = __shfl_sync(0xffffffffu, h, j);
        m = fmaf(rootT[j * 33 + lane], hj, m);
    }
    m = fmaxf(m, 0.f);

    float gr = bi[lane], gz = bi[32 + lane], gn = bi[64 + lane];
    float hr = bh[lane], hz = bh[32 + lane], hn = bh[64 + lane];
#pragma unroll
    for (int j = 0; j < 32; j++) {
        float mj = __shfl_sync(0xffffffffu, m, j);
        float hj = __shfl_sync(0xffffffffu, h, j);
        gr = fmaf(wihT[j * 97 + lane], mj, gr);
        gz = fmaf(wihT[j * 97 + 32 + lane], mj, gz);
        gn = fmaf(wihT[j * 97 + 64 + lane], mj, gn);
        hr = fmaf(whhT[j * 97 + lane], hj, hr);
        hz = fmaf(whhT[j * 97 + 32 + lane], hj, hz);
        hn = fmaf(whhT[j * 97 + 64 + lane], hj, hn);
    }
    float r = 1.f / (1.f + __expf(-(gr + hr)));
    float z = 1.f / (1.f + __expf(-(gz + hz)));
    float nn = tanhf(gn + r * hn);
    float hnew = (1.f - z) * nn + z * h;

    g_out[base] = hnew;
    g_agg[base] = 0.f;
}

// ============================================================
// final readout (unchanged)
// ============================================================
__global__ void k_final(const float* __restrict__ l1w, const float* __restrict__ l1b,
                        const float* __restrict__ l2w, const float* __restrict__ l2b,
                        float* __restrict__ out, int n) {
    __shared__ float w1T[32 * 33];
    __shared__ float b1s[32], w2s[32];
    int t = threadIdx.x;
    for (int i = t; i < 1024; i += blockDim.x) {
        int d = i >> 5, j = i & 31;
        w1T[j * 33 + d] = l1w[i];
    }
    if (t < 32) { b1s[t] = l1b[t]; w2s[t] = l2w[t]; }
    __syncthreads();

    int warp = (blockIdx.x * blockDim.x + t) >> 5;
    int lane = t & 31;
    if (warp >= n) return;
    float h = g_out[(size_t)warp * 32 + lane];
    float acc = b1s[lane];
#pragma unroll
    for (int j = 0; j < 32; j++) {
        float hj = __shfl_sync(0xffffffffu, h, j);
        acc = fmaf(w1T[j * 33 + lane], hj, acc);
    }
    acc = fmaxf(acc, 0.f);
    float p = acc * w2s[lane];
#pragma unroll
    for (int off = 16; off; off >>= 1) p += __shfl_xor_sync(0xffffffffu, p, off);
    if (lane == 0) out[warp] = p + __ldg(&l2b[0]);
}

// ============================================================
// launcher
// ============================================================
extern "C" void kernel_launch(void* const* d_in, const int* in_sizes, int n_in,
                              void* d_out, int out_size) {
    const float* x      = (const float*)d_in[0];
    const int*   ei     = (const int*)  d_in[1];
    const float* ea     = (const float*)d_in[2];
    const float* lin0_w = (const float*)d_in[3];
    const float* lin0_b = (const float*)d_in[4];
    const float* mlp_w1 = (const float*)d_in[5];
    const float* mlp_b1 = (const float*)d_in[6];
    const float* mlp_w2 = (const float*)d_in[7];
    const float* mlp_b2 = (const float*)d_in[8];
    const float* root_w = (const float*)d_in[9];
    const float* conv_b = (const float*)d_in[10];
    const float* gw_ih  = (const float*)d_in[11];
    const float* gw_hh  = (const float*)d_in[12];
    const float* gb_ih  = (const float*)d_in[13];
    const float* gb_hh  = (const float*)d_in[14];
    const float* lin1_w = (const float*)d_in[15];
    const float* lin1_b = (const float*)d_in[16];
    const float* lin2_w = (const float*)d_in[17];
    const float* lin2_b = (const float*)d_in[18];

    const int n = in_sizes[0] / 16;   // 100000
    const int e = in_sizes[2] / 5;    // 200000
    const int* src = ei;
    const int* dst = ei + e;

    cudaFuncSetAttribute(k_we, cudaFuncAttributeMaxDynamicSharedMemorySize, WE_SMEM_BYTES);

    k_init<<<1024, 256>>>(n);
    k_count<<<(e + 255) / 256, 256>>>(dst, e);
    k_lin0<<<(n * 32 + 255) / 256, 256>>>(x, lin0_w, lin0_b, n);
    k_prep<<<(1024 * 128 + 255) / 256, 256>>>(mlp_w2, mlp_b2);

    k_we<<<(e + 127) / 128, 256, WE_SMEM_BYTES>>>(ea, mlp_w1, mlp_b1, e);

    for (int it = 0; it < 3; it++) {
        k_msg<<<(e * 32 + 255) / 256, 256>>>(src, dst, e);
        k_update<<<(n * 32 + 511) / 512, 512>>>(root_w, conv_b, gw_ih, gw_hh, gb_ih, gb_hh, n);
    }

    k_final<<<(n * 32 + 255) / 256, 256>>>(lin1_w, lin1_b, lin2_w, lin2_b, (float*)d_out, n);
}

// round 11
// speedup vs baseline: 2.5306x; 1.0525x over previous
#include <cuda_runtime.h>
#include <cuda_fp16.h>
#include <cstdint>

// Problem constants
#define MAXN 100000
#define MAXE 200000

// -------- scratch (static device globals; no allocation) --------
// w_e stored fp16, TRANSPOSED per edge: g_weh[e][o][i] at flat col n = o*32+i
__device__ __half g_weh[(size_t)MAXE * 1024];   // 409.6 MB
__device__ __half g_w2h[1024 * 128];            // fp16 W2, rows PERMUTED by sr(n)
__device__ float g_b2p[1024];                   // permuted b2
__device__ float g_out[MAXN * 32];
__device__ float g_agg[MAXN * 32];
__device__ float g_cnt[MAXN];

__device__ __forceinline__ uint32_t smem_u32(const void* p) {
    uint32_t a;
    asm("{ .reg .u64 t; cvta.to.shared.u64 t, %1; cvt.u32.u64 %0, t; }" : "=r"(a) : "l"(p));
    return a;
}
__device__ __forceinline__ void ldsm_x4(uint32_t& r0, uint32_t& r1, uint32_t& r2, uint32_t& r3,
                                        uint32_t addr) {
    asm volatile("ldmatrix.sync.aligned.m8n8.x4.shared.b16 {%0,%1,%2,%3}, [%4];"
        : "=r"(r0), "=r"(r1), "=r"(r2), "=r"(r3) : "r"(addr));
}
__device__ __forceinline__ void mma16816(float* d, const uint32_t* a, const uint32_t* b) {
    asm volatile("mma.sync.aligned.m16n8k16.row.col.f32.f16.f16.f32 "
        "{%0,%1,%2,%3}, {%4,%5,%6,%7}, {%8,%9}, {%0,%1,%2,%3};"
        : "+f"(d[0]), "+f"(d[1]), "+f"(d[2]), "+f"(d[3])
        : "r"(a[0]), "r"(a[1]), "r"(a[2]), "r"(a[3]), "r"(b[0]), "r"(b[1]));
}
#define CP_ASYNC16(dst, src) \
    asm volatile("cp.async.cg.shared.global [%0], [%1], 16;" :: "r"(dst), "l"(src))
#define CP_COMMIT() asm volatile("cp.async.commit_group;")
#define CP_WAIT0()  asm volatile("cp.async.wait_group 0;")

// ============================================================
// prep: W2 fp32 [1024,128] -> fp16, rows permuted by sr(n); also permuted b2
// ============================================================
__global__ void k_prep(const float* __restrict__ w2, const float* __restrict__ b2) {
    int i = blockIdx.x * blockDim.x + threadIdx.x;
    if (i >= 1024 * 128) return;
    int n = i >> 7, k = i & 127;
    int sr = ((n & 31) << 5) | (n >> 5);
    g_w2h[n * 128 + k] = __float2half(w2[(size_t)sr * 128 + k]);
    if (k == 0) g_b2p[n] = b2[sr];
}

// ============================================================
// init / count / lin0
// ============================================================
__global__ void k_init(int n) {
    int t = blockIdx.x * blockDim.x + threadIdx.x;
    int stride = gridDim.x * blockDim.x;
    for (int i = t; i < n * 32; i += stride) g_agg[i] = 0.f;
    for (int i = t; i < n; i += stride) g_cnt[i] = 0.f;
}
__global__ void k_count(const int* __restrict__ dst, int e) {
    int t = blockIdx.x * blockDim.x + threadIdx.x;
    if (t < e) atomicAdd(&g_cnt[dst[t]], 1.f);
}
__global__ void k_lin0(const float* __restrict__ x, const float* __restrict__ w,
                       const float* __restrict__ b, int n) {
    __shared__ float wT[16 * 32];
    __shared__ float bs[32];
    int t = threadIdx.x;
    for (int i = t; i < 512; i += blockDim.x) {
        int d = i >> 4, k = i & 15;
        wT[k * 32 + d] = w[i];
    }
    if (t < 32) bs[t] = b[t];
    __syncthreads();
    int warp = (blockIdx.x * blockDim.x + t) >> 5;
    int lane = t & 31;
    if (warp >= n) return;
    float xk = (lane < 16) ? x[(size_t)warp * 16 + lane] : 0.f;
    float acc = bs[lane];
#pragma unroll
    for (int k = 0; k < 16; k++) {
        float xv = __shfl_sync(0xffffffffu, xk, k);
        acc = fmaf(wT[k * 32 + lane], xv, acc);
    }
    g_out[(size_t)warp * 32 + lane] = fmaxf(acc, 0.f);
}

// ============================================================
// w_e GEMM via mma.sync: one CTA = 128 edges x FULL 1024 cols, K=128.
// A computed once per CTA; B streamed via cp.async double-buffer.
// Epilogue routed through the consumed B buffer -> coalesced STG.128.
// ============================================================
#define STR_H 136
#define BUF_HALVES (128 * STR_H)
#define WE_SMEM_BYTES (3 * BUF_HALVES * 2)   // A + 2 B buffers

__global__ __launch_bounds__(256, 2) void k_we(
    const float* __restrict__ ea, const float* __restrict__ w1,
    const float* __restrict__ b1, int E)
{
    extern __shared__ __half smh[];
    __half* Asm = smh;                    // [128 el][136 k]
    __half* Bsm[2] = { smh + BUF_HALVES, smh + 2 * BUF_HALVES };
    __shared__ float eas[128 * 5];
    __shared__ float w1s[128 * 5];
    __shared__ float b1s[128];

    const int tid = threadIdx.x;
    const int w = tid >> 5;
    const int lane = tid & 31;
    const int ebase = blockIdx.x * 128;

#define STAGE_B(chunk, buf) do { \
        const __half* gsrc = g_w2h + (size_t)(chunk) * 128 * 128; \
        for (int i = tid; i < 2048; i += 256) { \
            int n = i >> 4, k0 = (i & 15) * 8; \
            uint32_t dsa = smem_u32(&Bsm[buf][n * STR_H + k0]); \
            CP_ASYNC16(dsa, gsrc + n * 128 + k0); \
        } \
        CP_COMMIT(); \
    } while (0)

    STAGE_B(0, 0);

    // stage edge_attr + edge-MLP layer-1 weights
    for (int i = tid; i < 640; i += 256) {
        int el = i / 5, j = i - el * 5;
        int ge = ebase + el;
        eas[i] = (ge < E) ? ea[(size_t)ge * 5 + j] : 0.f;
        w1s[i] = __ldg(&w1[i]);
    }
    if (tid < 128) b1s[tid] = __ldg(&b1[tid]);
    __syncthreads();

    // compute r (edge MLP hidden) -> Asm fp16  (once per CTA)
    for (int i = tid; i < 16384; i += 256) {
        int el = i >> 7, h = i & 127;
        float a = b1s[h];
        const float* e5 = &eas[el * 5];
        const float* w5 = &w1s[h * 5];
#pragma unroll
        for (int j = 0; j < 5; j++)
            a = fmaf(e5[j], w5[j], a);
        Asm[el * STR_H + h] = __float2half(fmaxf(a, 0.f));
    }
    CP_WAIT0();
    __syncthreads();

    const uint32_t Abase = smem_u32(Asm);
    const int R = (w & 3) * 32;      // warp M offset
    const int C = (w >> 2) * 64;     // warp N offset within chunk
    const int lt = lane >> 3;
    const int lr = lane & 7;
    const int qr = lane >> 2, qc = (lane & 3) * 2;

    for (int chunk = 0; chunk < 8; chunk++) {
        const int cur = chunk & 1;
        const uint32_t Bbase = smem_u32(Bsm[cur]);
        // prefetch next chunk into the other buffer
        if (chunk < 7) STAGE_B(chunk + 1, cur ^ 1);

        float acc[2][8][4];
#pragma unroll
        for (int rt = 0; rt < 2; rt++)
#pragma unroll
            for (int nt = 0; nt < 8; nt++)
#pragma unroll
                for (int q = 0; q < 4; q++) acc[rt][nt][q] = 0.f;

#pragma unroll
        for (int ks = 0; ks < 8; ks++) {
            uint32_t a[2][4];
#pragma unroll
            for (int rt = 0; rt < 2; rt++) {
                int row = R + rt * 16 + (lt & 1) * 8 + lr;
                int kseg = lt >> 1;
                ldsm_x4(a[rt][0], a[rt][1], a[rt][2], a[rt][3],
                        Abase + (row * STR_H + ks * 16 + kseg * 8) * 2);
            }
            uint32_t b[8][2];
#pragma unroll
            for (int np = 0; np < 4; np++) {
                int n = C + np * 16 + (lt >> 1) * 8 + lr;
                int kseg = lt & 1;
                uint32_t r0, r1, r2, r3;
                ldsm_x4(r0, r1, r2, r3, Bbase + (n * STR_H + ks * 16 + kseg * 8) * 2);
                b[2 * np][0] = r0; b[2 * np][1] = r1;
                b[2 * np + 1][0] = r2; b[2 * np + 1][1] = r3;
            }
#pragma unroll
            for (int rt = 0; rt < 2; rt++)
#pragma unroll
                for (int nt = 0; nt < 8; nt++)
                    mma16816(acc[rt][nt], a[rt], b[nt]);
        }

        // ---- epilogue via smem (reuse consumed B buffer) ----
        __syncthreads();   // all warps done ldmatrix-ing Bsm[cur]
        {
            __half* Esm = Bsm[cur];
            const int colbase = chunk * 128;
#pragma unroll
            for (int rt = 0; rt < 2; rt++) {
#pragma unroll
                for (int h8 = 0; h8 < 2; h8++) {
                    int row = R + rt * 16 + h8 * 8 + qr;
#pragma unroll
                    for (int nt = 0; nt < 8; nt++) {
                        int c = C + nt * 8 + qc;
                        float d0 = acc[rt][nt][h8 * 2 + 0] + __ldg(&g_b2p[colbase + c]);
                        float d1 = acc[rt][nt][h8 * 2 + 1] + __ldg(&g_b2p[colbase + c + 1]);
                        *(__half2*)&Esm[row * STR_H + c] = __floats2half2_rn(d0, d1);
                    }
                }
            }
            __syncthreads();
            // coalesced copy: 128 rows x 256B, 16B per thread-iteration
            for (int i = tid; i < 2048; i += 256) {
                int row = i >> 4, seg = i & 15;
                int ge = ebase + row;
                if (ge < E)
                    *(uint4*)(g_weh + (size_t)ge * 1024 + colbase + seg * 8) =
                        *(const uint4*)&Esm[row * STR_H + seg * 8];
            }
        }
        if (chunk < 7) {
            CP_WAIT0();
            __syncthreads();
        }
    }
#undef STAGE_B
}

// ============================================================
// message pass: lane-private coalesced fp16 streaming reads
// ============================================================
__global__ void k_msg(const int* __restrict__ src, const int* __restrict__ dst, int e) {
    int warp = (blockIdx.x * blockDim.x + threadIdx.x) >> 5;
    int lane = threadIdx.x & 31;
    if (warp >= e) return;
    int s = __ldg(&src[warp]);
    int d = __ldg(&dst[warp]);
    const uint4* wp = (const uint4*)(g_weh + (size_t)warp * 1024 + lane * 32);
    uint4 w0 = __ldcs(&wp[0]);
    uint4 w1 = __ldcs(&wp[1]);
    uint4 w2 = __ldcs(&wp[2]);
    uint4 w3 = __ldcs(&wp[3]);
    float sv = g_out[(size_t)s * 32 + lane];
    float acc = 0.f;
#define ACC2(u, i0) do { \
        float2 f_ = __half22float2(*(const __half2*)&(u)); \
        acc = fmaf(__shfl_sync(0xffffffffu, sv, (i0)), f_.x, acc); \
        acc = fmaf(__shfl_sync(0xffffffffu, sv, (i0) + 1), f_.y, acc); \
    } while (0)
    ACC2(w0.x, 0);  ACC2(w0.y, 2);  ACC2(w0.z, 4);  ACC2(w0.w, 6);
    ACC2(w1.x, 8);  ACC2(w1.y, 10); ACC2(w1.z, 12); ACC2(w1.w, 14);
    ACC2(w2.x, 16); ACC2(w2.y, 18); ACC2(w2.z, 20); ACC2(w2.w, 22);
    ACC2(w3.x, 24); ACC2(w3.y, 26); ACC2(w3.z, 28); ACC2(w3.w, 30);
#undef ACC2
    atomicAdd(&g_agg[(size_t)d * 32 + lane], acc);
}

// ============================================================
// fused NNConv-root + GRU update (1024-thread blocks)
// ============================================================
__global__ void k_update(const float* __restrict__ root_w, const float* __restrict__ conv_b,
                         const float* __restrict__ wih, const float* __restrict__ whh,
                         const float* __restrict__ bih, const float* __restrict__ bhh, int n) {
    __shared__ float rootT[32 * 33];
    __shared__ float wihT[32 * 97];
    __shared__ float whhT[32 * 97];
    __shared__ float cb[32], bi[96], bh[96];
    int t = threadIdx.x;
    for (int i = t; i < 1024; i += blockDim.x) {
        int d = i >> 5, j = i & 31;
        rootT[j * 33 + d] = root_w[i];
    }
    for (int i = t; i < 3072; i += blockDim.x) {
        int rr = i >> 5, j = i & 31;
        wihT[j * 97 + rr] = wih[i];
        whhT[j * 97 + rr] = whh[i];
    }
    if (t < 32) cb[t] = conv_b[t];
    if (t < 96) { bi[t] = bih[t]; bh[t] = bhh[t]; }
    __syncthreads();

    int warp = (blockIdx.x * blockDim.x + t) >> 5;
    int lane = t & 31;
    if (warp >= n) return;
    size_t base = (size_t)warp * 32 + lane;

    float h = g_out[base];
    float c = fmaxf(g_cnt[warp], 1.f);
    float m = g_agg[base] / c + cb[lane];
#pragma unroll
    for (int j = 0; j < 32; j++) {
        float hj = __shfl_sync(0xffffffffu, h, j);
        m = fmaf(rootT[j * 33 + lane], hj, m);
    }
    m = fmaxf(m, 0.f);

    float gr = bi[lane], gz = bi[32 + lane], gn = bi[64 + lane];
    float hr = bh[lane], hz = bh[32 + lane], hn = bh[64 + lane];
#pragma unroll
    for (int j = 0; j < 32; j++) {
        float mj = __shfl_sync(0xffffffffu, m, j);
        float hj = __shfl_sync(0xffffffffu, h, j);
        gr = fmaf(wihT[j * 97 + lane], mj, gr);
        gz = fmaf(wihT[j * 97 + 32 + lane], mj, gz);
        gn = fmaf(wihT[j * 97 + 64 + lane], mj, gn);
        hr = fmaf(whhT[j * 97 + lane], hj, hr);
        hz = fmaf(whhT[j * 97 + 32 + lane], hj, hz);
        hn = fmaf(whhT[j * 97 + 64 + lane], hj, hn);
    }
    float r = 1.f / (1.f + __expf(-(gr + hr)));
    float z = 1.f / (1.f + __expf(-(gz + hz)));
    float nn = tanhf(gn + r * hn);
    float hnew = (1.f - z) * nn + z * h;

    g_out[base] = hnew;
    g_agg[base] = 0.f;
}

// ============================================================
// final readout
// ============================================================
__global__ void k_final(const float* __restrict__ l1w, const float* __restrict__ l1b,
                        const float* __restrict__ l2w, const float* __restrict__ l2b,
                        float* __restrict__ out, int n) {
    __shared__ float w1T[32 * 33];
    __shared__ float b1s[32], w2s[32];
    int t = threadIdx.x;
    for (int i = t; i < 1024; i += blockDim.x) {
        int d = i >> 5, j = i & 31;
        w1T[j * 33 + d] = l1w[i];
    }
    if (t < 32) { b1s[t] = l1b[t]; w2s[t] = l2w[t]; }
    __syncthreads();

    int warp = (blockIdx.x * blockDim.x + t) >> 5;
    int lane = t & 31;
    if (warp >= n) return;
    float h = g_out[(size_t)warp * 32 + lane];
    float acc = b1s[lane];
#pragma unroll
    for (int j = 0; j < 32; j++) {
        float hj = __shfl_sync(0xffffffffu, h, j);
        acc = fmaf(w1T[j * 33 + lane], hj, acc);
    }
    acc = fmaxf(acc, 0.f);
    float p = acc * w2s[lane];
#pragma unroll
    for (int off = 16; off; off >>= 1) p += __shfl_xor_sync(0xffffffffu, p, off);
    if (lane == 0) out[warp] = p + __ldg(&l2b[0]);
}

// ============================================================
// launcher
// ============================================================
extern "C" void kernel_launch(void* const* d_in, const int* in_sizes, int n_in,
                              void* d_out, int out_size) {
    const float* x      = (const float*)d_in[0];
    const int*   ei     = (const int*)  d_in[1];
    const float* ea     = (const float*)d_in[2];
    const float* lin0_w = (const float*)d_in[3];
    const float* lin0_b = (const float*)d_in[4];
    const float* mlp_w1 = (const float*)d_in[5];
    const float* mlp_b1 = (const float*)d_in[6];
    const float* mlp_w2 = (const float*)d_in[7];
    const float* mlp_b2 = (const float*)d_in[8];
    const float* root_w = (const float*)d_in[9];
    const float* conv_b = (const float*)d_in[10];
    const float* gw_ih  = (const float*)d_in[11];
    const float* gw_hh  = (const float*)d_in[12];
    const float* gb_ih  = (const float*)d_in[13];
    const float* gb_hh  = (const float*)d_in[14];
    const float* lin1_w = (const float*)d_in[15];
    const float* lin1_b = (const float*)d_in[16];
    const float* lin2_w = (const float*)d_in[17];
    const float* lin2_b = (const float*)d_in[18];

    const int n = in_sizes[0] / 16;   // 100000
    const int e = in_sizes[2] / 5;    // 200000
    const int* src = ei;
    const int* dst = ei + e;

    cudaFuncSetAttribute(k_we, cudaFuncAttributeMaxDynamicSharedMemorySize, WE_SMEM_BYTES);

    k_init<<<1024, 256>>>(n);
    k_count<<<(e + 255) / 256, 256>>>(dst, e);
    k_lin0<<<(n * 32 + 255) / 256, 256>>>(x, lin0_w, lin0_b, n);
    k_prep<<<(1024 * 128 + 255) / 256, 256>>>(mlp_w2, mlp_b2);

    k_we<<<(e + 127) / 128, 256, WE_SMEM_BYTES>>>(ea, mlp_w1, mlp_b1, e);

    for (int it = 0; it < 3; it++) {
        k_msg<<<(e * 32 + 255) / 256, 256>>>(src, dst, e);
        k_update<<<(n * 32 + 1023) / 1024, 1024>>>(root_w, conv_b, gw_ih, gw_hh, gb_ih, gb_hh, n);
    }

    k_final<<<(n * 32 + 255) / 256, 256>>>(lin1_w, lin1_b, lin2_w, lin2_b, (float*)d_out, n);
}